// round 7
// baseline (speedup 1.0000x reference)
#include <cuda_runtime.h>

#define NB 2
#define NEG 0.2f

// ---------------- scratch (__device__ globals; no allocation) ----------------
// All intermediates are CHANNEL-LAST: [b][spatial][C]
__device__ float g_t1 [NB*64*64*64*64];
__device__ float g_x1 [NB*64*64*64*64];
__device__ float g_xd1[NB*32*32*32*128];
__device__ float g_t2 [NB*32*32*32*128];
__device__ float g_x2 [NB*32*32*32*128];
__device__ float g_xd2[NB*16*16*16*256];
__device__ float g_t3 [NB*16*16*16*256];
__device__ float g_x3 [NB*16*16*16*256];
__device__ float g_x4 [NB*8*8*8*128];
__device__ float g_m2 [NB*32*32*32];
__device__ float g_m3 [NB*16*16*16];
__device__ int   g_list1[NB*64*64*64];
__device__ int   g_list2[NB*32*32*32];
__device__ int   g_list3[NB*16*16*16];
__device__ int   g_cnt[3];
// repacked weights: [tap][cin][cout], cout contiguous
__device__ float g_w1a[27*3*64];
__device__ float g_w1b[27*64*64];
__device__ float g_w1d[3*64];
__device__ float g_wd1[27*64*128];
__device__ float g_w2a[27*128*128];
__device__ float g_w2b[27*128*128];
__device__ float g_wd2[27*128*256];
__device__ float g_w3a[27*256*256];
__device__ float g_w3b[27*256*256];
__device__ float g_wd3[27*256*128];

__device__ __forceinline__ float lrelu(float v){ return v >= 0.f ? v : NEG*v; }

// packed f32x2 helpers (sm_103a)
__device__ __forceinline__ unsigned long long dup2(float w){
    unsigned long long r;
    asm("mov.b64 %0, {%1, %1};" : "=l"(r) : "f"(w));
    return r;
}
__device__ __forceinline__ void ffma2(unsigned long long& d,
                                      unsigned long long a, unsigned long long b){
    asm("fma.rn.f32x2 %0, %1, %2, %0;" : "+l"(d) : "l"(a), "l"(b));
}
__device__ __forceinline__ float2 unpack2(unsigned long long v){
    float2 r;
    asm("mov.b64 {%0, %1}, %2;" : "=f"(r.x), "=f"(r.y) : "l"(v));
    return r;
}

// ---------------- setup kernels ----------------
struct RepackArgs {
    const float* src[10];
    float*       dst[10];
    int cin[10], cout[10], k3[10], start[10];
    int ntot;
};

__global__ void repack_all_k(RepackArgs a){
    int idx = blockIdx.x*blockDim.x + threadIdx.x;
    if (idx < 3) g_cnt[idx] = 0;
    if (idx >= a.ntot) return;
    int s = 0;
    #pragma unroll
    for (int k = 1; k < 10; k++) if (idx >= a.start[k]) s = k;
    int i = idx - a.start[s];
    int CIN = a.cin[s], COUT = a.cout[s], K3 = a.k3[s];
    int oc = i / (CIN*K3);
    int r  = i % (CIN*K3);
    int ic = r / K3;
    int k  = r % K3;
    a.dst[s][(k*CIN + ic)*COUT + oc] = a.src[s][i];
}

__global__ void down_mask_k(const float* __restrict__ in, float* __restrict__ out,
                            int Din, int Dout){
    int i = blockIdx.x*blockDim.x + threadIdx.x;
    int tot = NB*Dout*Dout*Dout;
    if (i >= tot) return;
    int ox = i % Dout, t = i / Dout;
    int oy = t % Dout; t /= Dout;
    int oz = t % Dout; int b = t / Dout;
    float m = 0.f;
    for (int kz = 0; kz < 3; kz++){
        int iz = 2*oz - 1 + kz; if ((unsigned)iz >= (unsigned)Din) continue;
        for (int ky = 0; ky < 3; ky++){
            int iy = 2*oy - 1 + ky; if ((unsigned)iy >= (unsigned)Din) continue;
            for (int kx = 0; kx < 3; kx++){
                int ix = 2*ox - 1 + kx; if ((unsigned)ix >= (unsigned)Din) continue;
                m = fmaxf(m, in[((b*Din + iz)*Din + iy)*Din + ix]);
            }
        }
    }
    out[i] = m;
}

__global__ void fuse_k(const float* __restrict__ mask, const float* __restrict__ m2,
                       float* __restrict__ m3, int* __restrict__ l1,
                       int* __restrict__ l2, int* __restrict__ cnt){
    const int A = NB*262144, B = NB*32768, C = NB*4096;
    int idx = blockIdx.x*blockDim.x + threadIdx.x;
    if (idx < A){
        if (mask[idx] != 0.f){ int p = atomicAdd(cnt+0, 1); l1[p] = idx; }
    } else if (idx < A+B){
        int i = idx - A;
        if (m2[i] != 0.f){ int p = atomicAdd(cnt+1, 1); l2[p] = i; }
    } else if (idx < A+B+C){
        int i = idx - A - B;
        int ox = i % 16, t = i / 16;
        int oy = t % 16; t /= 16;
        int oz = t % 16; int b = t / 16;
        float m = 0.f;
        for (int kz = 0; kz < 3; kz++){
            int iz = 2*oz - 1 + kz; if ((unsigned)iz >= 32u) continue;
            for (int ky = 0; ky < 3; ky++){
                int iy = 2*oy - 1 + ky; if ((unsigned)iy >= 32u) continue;
                for (int kx = 0; kx < 3; kx++){
                    int ix = 2*ox - 1 + kx; if ((unsigned)ix >= 32u) continue;
                    m = fmaxf(m, m2[((b*32 + iz)*32 + iy)*32 + ix]);
                }
            }
        }
        m3[i] = m;
    }
}

__global__ void build_list_k(const float* __restrict__ m, int tot,
                             int* __restrict__ list, int* __restrict__ cnt){
    int i = blockIdx.x*blockDim.x + threadIdx.x;
    if (i < tot && m[i] != 0.f){
        int p = atomicAdd(cnt, 1);
        list[p] = i;
    }
}

__global__ void fill_k(const float* __restrict__ in, const float* __restrict__ m,
                       float* __restrict__ out, int C, int n){
    int i  = blockIdx.x*blockDim.x + threadIdx.x;
    int st = gridDim.x*blockDim.x;
    for (int j = i; j < n; j += st){
        float v = in[j];
        float r = lrelu(v);
        if (m && m[j/C] == 0.f) r = 0.f;
        out[j] = r;
    }
}

// ---------------- simple conv (stage-1a: CIN=3, NCDHW in, grid-stride) -------
template<int CIN, int COUT, int CINC, int VB>
__global__ void __launch_bounds__(COUT) conv_s_k(
    const float* __restrict__ in, const float* __restrict__ wr,
    const float* __restrict__ in_mask,
    const int* __restrict__ list, const int* __restrict__ cnt,
    int Din, int Dout,
    float* __restrict__ out)
{
    __shared__ int s_base[VB];
    __shared__ int s_out [VB];
    __shared__ float s_in[VB][CINC];

    const int tid   = threadIdx.x;
    const int Din3  = Din*Din*Din;
    const int Dout3 = Dout*Dout*Dout;
    const int n     = *cnt;

    for (int vbase = blockIdx.x*VB; vbase < n; vbase += gridDim.x*VB){
        int vb=0,vz=0,vy=0,vx=0,vvalid=0;
        if (tid < VB){
            int vi = vbase + tid;
            int ob = -1;
            if (vi < n){
                int id = list[vi];
                vx = id % Dout; id /= Dout;
                vy = id % Dout; id /= Dout;
                vz = id % Dout; vb = id / Dout;
                ob = vb*Dout3 + (vz*Dout + vy)*Dout + vx;
                vvalid = 1;
            }
            s_out[tid] = ob;
        }
        __syncthreads();

        float acc[VB];
        #pragma unroll
        for (int v = 0; v < VB; v++) acc[v] = 0.f;

        for (int t = 0; t < 27; t++){
            int pred = 0;
            if (tid < VB){
                int base = -1;
                if (vvalid){
                    int kz = t/9, ky = (t/3)%3, kx = t%3;
                    int iz = vz - 1 + kz, iy = vy - 1 + ky, ix = vx - 1 + kx;
                    if ((unsigned)iz < (unsigned)Din && (unsigned)iy < (unsigned)Din &&
                        (unsigned)ix < (unsigned)Din){
                        int sp = (iz*Din + iy)*Din + ix;
                        if (in_mask[vb*Din3 + sp] != 0.f)
                            base = vb*CIN*Din3 + sp;   // NCDHW
                    }
                }
                s_base[tid] = base;
                pred = (base >= 0);
            }
            if (!__syncthreads_or(pred)) continue;

            float wreg[CINC];
            #pragma unroll
            for (int c = 0; c < CINC; c++)
                wreg[c] = wr[(t*CIN + c)*COUT + tid];
            #pragma unroll 1
            for (int i = tid; i < CINC*VB; i += COUT){
                int v = i / CINC, c = i % CINC;
                int base = s_base[v];
                s_in[v][c] = (base >= 0) ? in[base + c*Din3] : 0.f;
            }
            __syncthreads();
            #pragma unroll
            for (int v = 0; v < VB; v++){
                float a = acc[v];
                #pragma unroll
                for (int c = 0; c < CINC; c++)
                    a = fmaf(wreg[c], s_in[v][c], a);
                acc[v] = a;
            }
            __syncthreads();
        }

        #pragma unroll
        for (int v = 0; v < VB; v++){
            int ob = s_out[v];
            if (ob < 0) continue;
            out[ob*COUT + tid] = lrelu(acc[v]);
        }
        __syncthreads();
    }
}

// ---------------- f32x2 conv (channel-last, transposed staging, prefetch) ----
// thread = out channel. s_in is [c][v] so LDS.128 yields packed voxel pairs for
// fma.rn.f32x2 (2 MACs / fma-pipe slot). Gather+weights for iteration i+1 are
// prefetched into registers during compute of iteration i.
template<int CIN, int COUT, int CINC, int VB>
__global__ void __launch_bounds__(COUT) convp_k(
    const float* __restrict__ in, const float* __restrict__ wr,
    const float* __restrict__ in_mask,
    const int* __restrict__ list, const int* __restrict__ cnt,
    int Din, int Dout, int stride,
    const float* __restrict__ ident,
    const float* __restrict__ identx, const float* __restrict__ identw,
    float* __restrict__ out)
{
    constexpr int CHUNKS = CIN/CINC;
    constexpr int PT = (VB*CINC)/COUT;          // gather elems per thread
    static_assert((VB*CINC) % COUT == 0, "PT");
    static_assert(COUT % CINC == 0, "cmap");
    constexpr int VSTRIDE = COUT/CINC;          // v step between this thread's elems
    constexpr int ROW = VB + 4;                 // padded row (16B-aligned rows)

    __shared__ int s_tap[27];
    __shared__ int s_ntap;
    __shared__ int s_base[27][VB];
    __shared__ int s_out[VB];
    __shared__ __align__(16) float s_in[CINC][ROW];

    const int tid   = threadIdx.x;
    const int c0    = tid % CINC;               // this thread's staging channel
    const int v0    = tid / CINC;               // first staged voxel
    const int Din3  = Din*Din*Din;
    const int Dout3 = Dout*Dout*Dout;
    const int n     = list ? *cnt : NB*Dout3;

    for (int vbase = blockIdx.x*VB; vbase < n; vbase += gridDim.x*VB){
        int vb=0,vz=0,vy=0,vx=0,vvalid=0;
        if (tid < VB){
            int vi = vbase + tid;
            int ob = -1;
            if (vi < n){
                int id = list ? list[vi] : vi;
                vx = id % Dout; id /= Dout;
                vy = id % Dout; id /= Dout;
                vz = id % Dout; vb = id / Dout;
                ob = vb*Dout3 + (vz*Dout + vy)*Dout + vx;
                vvalid = 1;
            }
            s_out[tid] = ob;
        }
        if (tid == 0) s_ntap = 0;
        __syncthreads();

        for (int t = 0; t < 27; t++){
            int pred = 0;
            if (tid < VB){
                int base = -1;
                if (vvalid){
                    int kz = t/9, ky = (t/3)%3, kx = t%3;
                    int iz = vz*stride - 1 + kz;
                    int iy = vy*stride - 1 + ky;
                    int ix = vx*stride - 1 + kx;
                    if ((unsigned)iz < (unsigned)Din && (unsigned)iy < (unsigned)Din &&
                        (unsigned)ix < (unsigned)Din){
                        int sp = (iz*Din + iy)*Din + ix;
                        if (!in_mask || in_mask[vb*Din3 + sp] != 0.f)
                            base = (vb*Din3 + sp)*CIN;
                    }
                }
                s_base[t][tid] = base;
                pred = (base >= 0);
            }
            int any = __syncthreads_or(pred);
            if (any && tid == 0) s_tap[s_ntap++] = t;
        }
        __syncthreads();
        const int ntap = s_ntap;
        const int nit  = ntap * CHUNKS;

        unsigned long long acc2[VB/2];
        #pragma unroll
        for (int p = 0; p < VB/2; p++) acc2[p] = 0ull;

        float rin[PT], wv[CINC];
        auto fetch = [&](int it){
            int tap = s_tap[it/CHUNKS];
            int cc  = (it%CHUNKS)*CINC;
            #pragma unroll
            for (int k = 0; k < PT; k++){
                int base = s_base[tap][v0 + k*VSTRIDE];
                rin[k] = (base >= 0) ? in[base + cc + c0] : 0.f;
            }
            #pragma unroll
            for (int c = 0; c < CINC; c++)
                wv[c] = wr[(tap*CIN + cc + c)*COUT + tid];
        };

        if (nit > 0) fetch(0);
        for (int it = 0; it < nit; it++){
            __syncthreads();                     // prior compute done
            #pragma unroll
            for (int k = 0; k < PT; k++)
                s_in[c0][v0 + k*VSTRIDE] = rin[k];
            float wcur[CINC];
            #pragma unroll
            for (int c = 0; c < CINC; c++) wcur[c] = wv[c];
            __syncthreads();                     // staging visible
            if (it + 1 < nit) fetch(it + 1);     // overlap with compute
            #pragma unroll
            for (int c = 0; c < CINC; c++){
                unsigned long long wd = dup2(wcur[c]);
                const ulonglong2* row = reinterpret_cast<const ulonglong2*>(&s_in[c][0]);
                #pragma unroll
                for (int p = 0; p < VB/4; p++){
                    ulonglong2 u = row[p];
                    ffma2(acc2[2*p+0], wd, u.x);
                    ffma2(acc2[2*p+1], wd, u.y);
                }
            }
        }
        __syncthreads();

        float accf[VB];
        #pragma unroll
        for (int p = 0; p < VB/2; p++){
            float2 f = unpack2(acc2[p]);
            accf[2*p+0] = f.x;
            accf[2*p+1] = f.y;
        }
        #pragma unroll
        for (int v = 0; v < VB; v++){
            int ob = s_out[v];
            if (ob < 0) continue;
            float val = accf[v];
            if (ident) val += ident[ob*COUT + tid];
            if (identw){
                int b = ob / Dout3, sp = ob - b*Dout3;
                const float* xp = identx + b*3*Dout3 + sp;
                val = fmaf(identw[tid],          xp[0],       val);
                val = fmaf(identw[COUT + tid],   xp[Dout3],   val);
                val = fmaf(identw[2*COUT + tid], xp[2*Dout3], val);
            }
            out[ob*COUT + tid] = lrelu(val);
        }
        __syncthreads();
    }
}

// ---------------- final pooled reduce (channel-last x4) ----------------
__global__ void reduce_k(const float* __restrict__ x4, float* __restrict__ out){
    int b  = blockIdx.x;
    int oc = threadIdx.x;
    const float* p = x4 + b*512*128 + oc;
    float s = 0.f, mx = -3.402823466e38f;
    #pragma unroll 8
    for (int sp = 0; sp < 512; sp++){
        float v = p[sp*128];
        s += v; mx = fmaxf(mx, v);
    }
    out[b*256 + oc]       = s * (1.f/512.f);
    out[b*256 + 128 + oc] = mx;
}

// ---------------- launch ----------------
extern "C" void kernel_launch(void* const* d_in, const int* in_sizes, int n_in,
                              void* d_out, int out_size){
    const float* x    = (const float*)d_in[0];
    const float* mask = (const float*)d_in[1];
    const float* w[10] = {
        (const float*)d_in[2],  // w1a
        (const float*)d_in[4],  // w1d (K3=1)
        (const float*)d_in[3],  // w1b
        (const float*)d_in[5],  // wd1
        (const float*)d_in[6],  // w2a
        (const float*)d_in[7],  // w2b
        (const float*)d_in[8],  // wd2
        (const float*)d_in[9],  // w3a
        (const float*)d_in[10], // w3b
        (const float*)d_in[11], // wd3
    };
    float* out = (float*)d_out;

    float *t1,*x1,*xd1,*t2,*x2,*xd2,*t3,*x3,*x4,*m2,*m3;
    int *l1,*l2,*l3,*cnt;
    float *wr[10];
    cudaGetSymbolAddress((void**)&t1 , g_t1 );
    cudaGetSymbolAddress((void**)&x1 , g_x1 );
    cudaGetSymbolAddress((void**)&xd1, g_xd1);
    cudaGetSymbolAddress((void**)&t2 , g_t2 );
    cudaGetSymbolAddress((void**)&x2 , g_x2 );
    cudaGetSymbolAddress((void**)&xd2, g_xd2);
    cudaGetSymbolAddress((void**)&t3 , g_t3 );
    cudaGetSymbolAddress((void**)&x3 , g_x3 );
    cudaGetSymbolAddress((void**)&x4 , g_x4 );
    cudaGetSymbolAddress((void**)&m2 , g_m2 );
    cudaGetSymbolAddress((void**)&m3 , g_m3 );
    cudaGetSymbolAddress((void**)&l1 , g_list1);
    cudaGetSymbolAddress((void**)&l2 , g_list2);
    cudaGetSymbolAddress((void**)&l3 , g_list3);
    cudaGetSymbolAddress((void**)&cnt, g_cnt);
    cudaGetSymbolAddress((void**)&wr[0], g_w1a);
    cudaGetSymbolAddress((void**)&wr[1], g_w1d);
    cudaGetSymbolAddress((void**)&wr[2], g_w1b);
    cudaGetSymbolAddress((void**)&wr[3], g_wd1);
    cudaGetSymbolAddress((void**)&wr[4], g_w2a);
    cudaGetSymbolAddress((void**)&wr[5], g_w2b);
    cudaGetSymbolAddress((void**)&wr[6], g_wd2);
    cudaGetSymbolAddress((void**)&wr[7], g_w3a);
    cudaGetSymbolAddress((void**)&wr[8], g_w3b);
    cudaGetSymbolAddress((void**)&wr[9], g_wd3);

    RepackArgs ra;
    const int cins[10]  = {3, 3, 64, 64, 128, 128, 128, 256, 256, 256};
    const int couts[10] = {64,64, 64,128, 128, 128, 256, 256, 256, 128};
    const int k3s[10]   = {27, 1, 27, 27,  27,  27,  27,  27,  27,  27};
    int off = 0;
    for (int i = 0; i < 10; i++){
        ra.src[i] = w[i]; ra.dst[i] = wr[i];
        ra.cin[i] = cins[i]; ra.cout[i] = couts[i]; ra.k3[i] = k3s[i];
        ra.start[i] = off;
        off += cins[i]*couts[i]*k3s[i];
    }
    ra.ntot = off;

    repack_all_k<<<(ra.ntot + 255)/256, 256>>>(ra);
    down_mask_k<<<(NB*32768 + 255)/256, 256>>>(mask, m2, 64, 32);
    fuse_k<<<(NB*262144 + NB*32768 + NB*4096 + 255)/256, 256>>>(mask, m2, m3, l1, l2, cnt);
    build_list_k<<<(NB*4096 + 255)/256, 256>>>(m3, NB*4096, l3, cnt+2);

    // stage1a: VB=8 sparse
    conv_s_k<3,64,3,8><<<2048,64>>>(x, wr[0], mask, l1, cnt+0, 64, 64, t1);
    // stage1b: VB=8 sparse
    convp_k<64,64,16,8><<<4096,64>>>(t1, wr[2], mask, l1, cnt+0, 64,64,1,
                                     nullptr, x, wr[1], x1);
    // down1: VB=8 (input mask 5%)
    convp_k<64,128,16,8><<<2048,128>>>(x1, wr[3], mask, l2, cnt+1, 64,32,2,
                                       nullptr, nullptr, nullptr, xd1);
    // stage 2 (m2 ~75%)
    convp_k<128,128,16,64><<<1024,128>>>(xd1, wr[4], m2, l2, cnt+1, 32,32,1,
                                         nullptr, nullptr, nullptr, t2);
    fill_k<<<4096,256>>>(xd1, m2, x2, 128, NB*32768*128);
    convp_k<128,128,16,64><<<1024,128>>>(t2, wr[5], m2, l2, cnt+1, 32,32,1,
                                         xd1, nullptr, nullptr, x2);
    // down2 (dense)
    convp_k<128,256,16,32><<<256,256>>>(x2, wr[6], nullptr, nullptr, nullptr,
                                        32,16,2, nullptr, nullptr, nullptr, xd2);
    // stage 3 (dense)
    convp_k<256,256,16,32><<<256,256>>>(xd2, wr[7], nullptr, l3, cnt+2, 16,16,1,
                                        nullptr, nullptr, nullptr, t3);
    fill_k<<<2048,256>>>(xd2, nullptr, x3, 256, NB*4096*256);
    convp_k<256,256,16,32><<<256,256>>>(t3, wr[8], m3, l3, cnt+2, 16,16,1,
                                        xd2, nullptr, nullptr, x3);
    // down3 (dense)
    convp_k<256,128,16,8><<<128,128>>>(x3, wr[9], nullptr, nullptr, nullptr,
                                       16,8,2, nullptr, nullptr, nullptr, x4);
    reduce_k<<<2,128>>>(x4, out);
}

// round 10
// speedup vs baseline: 2.1026x; 2.1026x over previous
#include <cuda_runtime.h>
#include <cuda_bf16.h>
#include <cstdint>

#define NB 2
#define NEG 0.2f

// ---------------- scratch (__device__ globals; no allocation) ----------------
__device__ float g_t1 [NB*64*64*64*64];
__device__ float g_x1 [NB*64*64*64*64];
__device__ float g_xd1[NB*32*32*32*128];
__device__ float g_t2 [NB*32*32*32*128];
__device__ float g_x2 [NB*32*32*32*128];
__device__ float g_xd2[NB*16*16*16*256];
__device__ float g_t3 [NB*16*16*16*256];
__device__ float g_x3 [NB*16*16*16*256];
__device__ float g_x4 [NB*8*8*8*128];
__device__ float g_m2 [NB*32*32*32];
__device__ float g_m3 [NB*16*16*16];
__device__ int   g_list1[NB*64*64*64];
__device__ int   g_list2[NB*32*32*32];
__device__ int   g_list3[NB*16*16*16];
__device__ int   g_cnt[3];
// fp32 repacked weights (scalar convs): [tap][cin][cout]
__device__ float g_w1a[27*3*64];
__device__ float g_w1b[27*64*64];
__device__ float g_w1d[3*64];
__device__ float g_wd1[27*64*128];
__device__ float g_wd3[27*256*128];
// bf16 hi/lo MMA weights: [tap][chunk64][COUT][64]
__device__ __nv_bfloat16 g_w2a_h[27*2*128*64], g_w2a_l[27*2*128*64];
__device__ __nv_bfloat16 g_w2b_h[27*2*128*64], g_w2b_l[27*2*128*64];
__device__ __nv_bfloat16 g_wd2_h[27*2*256*64], g_wd2_l[27*2*256*64];
__device__ __nv_bfloat16 g_w3a_h[27*4*256*64], g_w3a_l[27*4*256*64];
__device__ __nv_bfloat16 g_w3b_h[27*4*256*64], g_w3b_l[27*4*256*64];
// bf16 hi/lo inputs (channel-last)
__device__ __nv_bfloat16 g_xd1h[NB*32768*128], g_xd1l[NB*32768*128];
__device__ __nv_bfloat16 g_t2h [NB*32768*128], g_t2l [NB*32768*128];
__device__ __nv_bfloat16 g_x2h [NB*32768*128], g_x2l [NB*32768*128];
__device__ __nv_bfloat16 g_xd2h[NB*4096*256],  g_xd2l[NB*4096*256];
__device__ __nv_bfloat16 g_t3h [NB*4096*256],  g_t3l [NB*4096*256];

__device__ __forceinline__ float lrelu(float v){ return v >= 0.f ? v : NEG*v; }
__device__ __forceinline__ unsigned sm_addr(const void* p){
    return (unsigned)__cvta_generic_to_shared(p);
}

// ---------------- mma.sync helpers (portable sm_80+) ----------------
__device__ __forceinline__ void ldsm_x4(uint32_t a, uint32_t& r0, uint32_t& r1,
                                        uint32_t& r2, uint32_t& r3){
    asm volatile("ldmatrix.sync.aligned.m8n8.x4.shared.b16 {%0,%1,%2,%3}, [%4];"
                 : "=r"(r0), "=r"(r1), "=r"(r2), "=r"(r3) : "r"(a));
}
__device__ __forceinline__ void ldsm_x2(uint32_t a, uint32_t& r0, uint32_t& r1){
    asm volatile("ldmatrix.sync.aligned.m8n8.x2.shared.b16 {%0,%1}, [%2];"
                 : "=r"(r0), "=r"(r1) : "r"(a));
}
__device__ __forceinline__ void mma_bf16(float* c, const uint32_t* a,
                                         uint32_t b0, uint32_t b1){
    asm volatile(
        "mma.sync.aligned.m16n8k16.row.col.f32.bf16.bf16.f32 "
        "{%0,%1,%2,%3},{%4,%5,%6,%7},{%8,%9},{%0,%1,%2,%3};"
        : "+f"(c[0]), "+f"(c[1]), "+f"(c[2]), "+f"(c[3])
        : "r"(a[0]), "r"(a[1]), "r"(a[2]), "r"(a[3]), "r"(b0), "r"(b1));
}

// ---------------- setup kernels ----------------
struct RepackArgs {
    const float* src[5];
    float*       dst[5];
    int cin[5], cout[5], k3[5], start[5];
    int ntot;
};
__global__ void repack_all_k(RepackArgs a){
    int idx = blockIdx.x*blockDim.x + threadIdx.x;
    if (idx < 3) g_cnt[idx] = 0;
    if (idx >= a.ntot) return;
    int s = 0;
    #pragma unroll
    for (int k = 1; k < 5; k++) if (idx >= a.start[k]) s = k;
    int i = idx - a.start[s];
    int CIN = a.cin[s], COUT = a.cout[s], K3 = a.k3[s];
    int oc = i / (CIN*K3);
    int r  = i % (CIN*K3);
    int ic = r / K3;
    int k  = r % K3;
    a.dst[s][(k*CIN + ic)*COUT + oc] = a.src[s][i];
}

struct RepackMMA {
    const float* src[5];
    __nv_bfloat16 *dh[5], *dl[5];
    int cin[5], cout[5], start[5];
    int ntot;
};
__global__ void repack_mma_k(RepackMMA a){
    int idx = blockIdx.x*blockDim.x + threadIdx.x;
    if (idx >= a.ntot) return;
    int s = 0;
    #pragma unroll
    for (int k = 1; k < 5; k++) if (idx >= a.start[k]) s = k;
    int i = idx - a.start[s];
    int CIN = a.cin[s], COUT = a.cout[s];
    int oc = i / (CIN*27);
    int r  = i % (CIN*27);
    int ic = r / 27;
    int t  = r % 27;
    float v = a.src[s][i];
    __nv_bfloat16 h = __float2bfloat16(v);
    __nv_bfloat16 l = __float2bfloat16(v - __bfloat162float(h));
    int di = ((t*(CIN/64) + ic/64)*COUT + oc)*64 + (ic % 64);
    a.dh[s][di] = h;
    a.dl[s][di] = l;
}

__global__ void cvt_k(const float* __restrict__ in, __nv_bfloat16* __restrict__ hi,
                      __nv_bfloat16* __restrict__ lo, int n){
    int i  = blockIdx.x*blockDim.x + threadIdx.x;
    int st = gridDim.x*blockDim.x;
    for (int j = i; j < n; j += st){
        float v = in[j];
        __nv_bfloat16 h = __float2bfloat16(v);
        hi[j] = h;
        lo[j] = __float2bfloat16(v - __bfloat162float(h));
    }
}

__global__ void down_mask_k(const float* __restrict__ in, float* __restrict__ out,
                            int Din, int Dout){
    int i = blockIdx.x*blockDim.x + threadIdx.x;
    int tot = NB*Dout*Dout*Dout;
    if (i >= tot) return;
    int ox = i % Dout, t = i / Dout;
    int oy = t % Dout; t /= Dout;
    int oz = t % Dout; int b = t / Dout;
    float m = 0.f;
    for (int kz = 0; kz < 3; kz++){
        int iz = 2*oz - 1 + kz; if ((unsigned)iz >= (unsigned)Din) continue;
        for (int ky = 0; ky < 3; ky++){
            int iy = 2*oy - 1 + ky; if ((unsigned)iy >= (unsigned)Din) continue;
            for (int kx = 0; kx < 3; kx++){
                int ix = 2*ox - 1 + kx; if ((unsigned)ix >= (unsigned)Din) continue;
                m = fmaxf(m, in[((b*Din + iz)*Din + iy)*Din + ix]);
            }
        }
    }
    out[i] = m;
}

__global__ void fuse_k(const float* __restrict__ mask, const float* __restrict__ m2,
                       float* __restrict__ m3, int* __restrict__ l1,
                       int* __restrict__ l2, int* __restrict__ cnt){
    const int A = NB*262144, B = NB*32768, C = NB*4096;
    int idx = blockIdx.x*blockDim.x + threadIdx.x;
    if (idx < A){
        if (mask[idx] != 0.f){ int p = atomicAdd(cnt+0, 1); l1[p] = idx; }
    } else if (idx < A+B){
        int i = idx - A;
        if (m2[i] != 0.f){ int p = atomicAdd(cnt+1, 1); l2[p] = i; }
    } else if (idx < A+B+C){
        int i = idx - A - B;
        int ox = i % 16, t = i / 16;
        int oy = t % 16; t /= 16;
        int oz = t % 16; int b = t / 16;
        float m = 0.f;
        for (int kz = 0; kz < 3; kz++){
            int iz = 2*oz - 1 + kz; if ((unsigned)iz >= 32u) continue;
            for (int ky = 0; ky < 3; ky++){
                int iy = 2*oy - 1 + ky; if ((unsigned)iy >= 32u) continue;
                for (int kx = 0; kx < 3; kx++){
                    int ix = 2*ox - 1 + kx; if ((unsigned)ix >= 32u) continue;
                    m = fmaxf(m, m2[((b*32 + iz)*32 + iy)*32 + ix]);
                }
            }
        }
        m3[i] = m;
    }
}

__global__ void build_list_k(const float* __restrict__ m, int tot,
                             int* __restrict__ list, int* __restrict__ cnt){
    int i = blockIdx.x*blockDim.x + threadIdx.x;
    if (i < tot && m[i] != 0.f){
        int p = atomicAdd(cnt, 1);
        list[p] = i;
    }
}

__global__ void fill_k(const float* __restrict__ in, const float* __restrict__ m,
                       float* __restrict__ out, int C, int n){
    int i  = blockIdx.x*blockDim.x + threadIdx.x;
    int st = gridDim.x*blockDim.x;
    for (int j = i; j < n; j += st){
        float v = in[j];
        float r = lrelu(v);
        if (m && m[j/C] == 0.f) r = 0.f;
        out[j] = r;
    }
}

// ---------------- simple conv (stage-1a: CIN=3, NCDHW in) ----------------
template<int CIN, int COUT, int CINC, int VB>
__global__ void __launch_bounds__(COUT) conv_s_k(
    const float* __restrict__ in, const float* __restrict__ wr,
    const float* __restrict__ in_mask,
    const int* __restrict__ list, const int* __restrict__ cnt,
    int Din, int Dout,
    float* __restrict__ out)
{
    __shared__ int s_base[VB];
    __shared__ int s_out [VB];
    __shared__ float s_in[VB][CINC];

    const int tid   = threadIdx.x;
    const int Din3  = Din*Din*Din;
    const int Dout3 = Dout*Dout*Dout;
    const int n     = *cnt;

    for (int vbase = blockIdx.x*VB; vbase < n; vbase += gridDim.x*VB){
        int vb=0,vz=0,vy=0,vx=0,vvalid=0;
        if (tid < VB){
            int vi = vbase + tid;
            int ob = -1;
            if (vi < n){
                int id = list[vi];
                vx = id % Dout; id /= Dout;
                vy = id % Dout; id /= Dout;
                vz = id % Dout; vb = id / Dout;
                ob = vb*Dout3 + (vz*Dout + vy)*Dout + vx;
                vvalid = 1;
            }
            s_out[tid] = ob;
        }
        __syncthreads();

        float acc[VB];
        #pragma unroll
        for (int v = 0; v < VB; v++) acc[v] = 0.f;

        for (int t = 0; t < 27; t++){
            int pred = 0;
            if (tid < VB){
                int base = -1;
                if (vvalid){
                    int kz = t/9, ky = (t/3)%3, kx = t%3;
                    int iz = vz - 1 + kz, iy = vy - 1 + ky, ix = vx - 1 + kx;
                    if ((unsigned)iz < (unsigned)Din && (unsigned)iy < (unsigned)Din &&
                        (unsigned)ix < (unsigned)Din){
                        int sp = (iz*Din + iy)*Din + ix;
                        if (in_mask[vb*Din3 + sp] != 0.f)
                            base = vb*CIN*Din3 + sp;
                    }
                }
                s_base[tid] = base;
                pred = (base >= 0);
            }
            if (!__syncthreads_or(pred)) continue;

            float wreg[CINC];
            #pragma unroll
            for (int c = 0; c < CINC; c++)
                wreg[c] = wr[(t*CIN + c)*COUT + tid];
            #pragma unroll 1
            for (int i = tid; i < CINC*VB; i += COUT){
                int v = i / CINC, c = i % CINC;
                int base = s_base[v];
                s_in[v][c] = (base >= 0) ? in[base + c*Din3] : 0.f;
            }
            __syncthreads();
            #pragma unroll
            for (int v = 0; v < VB; v++){
                float a = acc[v];
                #pragma unroll
                for (int c = 0; c < CINC; c++)
                    a = fmaf(wreg[c], s_in[v][c], a);
                acc[v] = a;
            }
            __syncthreads();
        }

        #pragma unroll
        for (int v = 0; v < VB; v++){
            int ob = s_out[v];
            if (ob < 0) continue;
            out[ob*COUT + tid] = lrelu(acc[v]);
        }
        __syncthreads();
    }
}

// ---------------- scalar pipelined conv (sparse stages) ----------------
template<int CIN, int COUT, int CINC, int VB>
__global__ void __launch_bounds__(COUT) convp_k(
    const float* __restrict__ in, const float* __restrict__ wr,
    const float* __restrict__ in_mask,
    const int* __restrict__ list, const int* __restrict__ cnt,
    int Din, int Dout, int stride,
    const float* __restrict__ ident,
    const float* __restrict__ identx, const float* __restrict__ identw,
    float* __restrict__ out)
{
    constexpr int CHUNKS = CIN/CINC;
    constexpr int F4 = VB*CINC/4;
    constexpr int PT = (F4 + COUT - 1)/COUT;
    __shared__ int s_tap[27];
    __shared__ int s_ntap;
    __shared__ int s_base[27][VB];
    __shared__ int s_out[VB];
    __shared__ __align__(16) float4 s_in[2][F4];

    const int tid   = threadIdx.x;
    const int Din3  = Din*Din*Din;
    const int Dout3 = Dout*Dout*Dout;
    const int n     = list ? *cnt : NB*Dout3;

    for (int vbase = blockIdx.x*VB; vbase < n; vbase += gridDim.x*VB){
        int vb=0,vz=0,vy=0,vx=0,vvalid=0;
        if (tid < VB){
            int vi = vbase + tid;
            int ob = -1;
            if (vi < n){
                int id = list ? list[vi] : vi;
                vx = id % Dout; id /= Dout;
                vy = id % Dout; id /= Dout;
                vz = id % Dout; vb = id / Dout;
                ob = vb*Dout3 + (vz*Dout + vy)*Dout + vx;
                vvalid = 1;
            }
            s_out[tid] = ob;
        }
        if (tid == 0) s_ntap = 0;
        __syncthreads();

        for (int t = 0; t < 27; t++){
            int pred = 0;
            if (tid < VB){
                int base = -1;
                if (vvalid){
                    int kz = t/9, ky = (t/3)%3, kx = t%3;
                    int iz = vz*stride - 1 + kz;
                    int iy = vy*stride - 1 + ky;
                    int ix = vx*stride - 1 + kx;
                    if ((unsigned)iz < (unsigned)Din && (unsigned)iy < (unsigned)Din &&
                        (unsigned)ix < (unsigned)Din){
                        int sp = (iz*Din + iy)*Din + ix;
                        if (!in_mask || in_mask[vb*Din3 + sp] != 0.f)
                            base = (vb*Din3 + sp)*CIN;
                    }
                }
                s_base[t][tid] = base;
                pred = (base >= 0);
            }
            int any = __syncthreads_or(pred);
            if (any && tid == 0) s_tap[s_ntap++] = t;
        }
        __syncthreads();
        const int ntap = s_ntap;
        const int nit  = ntap * CHUNKS;

        float acc[VB];
        #pragma unroll
        for (int v = 0; v < VB; v++) acc[v] = 0.f;

        auto issue = [&](int it, int buf){
            int tap = s_tap[it/CHUNKS];
            int cc  = (it%CHUNKS)*CINC;
            #pragma unroll
            for (int k = 0; k < PT; k++){
                int j = tid + k*COUT;
                if ((F4 % COUT == 0) || (j < F4)){
                    int v = j/(CINC/4), c4 = j%(CINC/4);
                    int base = s_base[tap][v];
                    const float* src = (base >= 0) ? (in + base + cc + c4*4) : in;
                    int sz = (base >= 0) ? 16 : 0;
                    unsigned dst = sm_addr(&s_in[buf][j]);
                    asm volatile("cp.async.ca.shared.global [%0], [%1], 16, %2;\n"
                                 :: "r"(dst), "l"(src), "r"(sz));
                }
            }
            asm volatile("cp.async.commit_group;\n");
        };

        if (nit > 0) issue(0, 0);
        for (int it = 0; it < nit; it++){
            int buf = it & 1;
            int tap = s_tap[it/CHUNKS];
            int cc  = (it%CHUNKS)*CINC;
            float wreg[CINC];
            #pragma unroll
            for (int c = 0; c < CINC; c++)
                wreg[c] = wr[(tap*CIN + cc + c)*COUT + tid];
            if (it + 1 < nit){
                issue(it + 1, buf ^ 1);
                asm volatile("cp.async.wait_group 1;\n");
            } else {
                asm volatile("cp.async.wait_group 0;\n");
            }
            __syncthreads();
            const float4* rows = s_in[buf];
            #pragma unroll
            for (int v = 0; v < VB; v++){
                float a = acc[v];
                #pragma unroll
                for (int q = 0; q < CINC/4; q++){
                    float4 r = rows[v*(CINC/4) + q];
                    a = fmaf(wreg[4*q+0], r.x, a);
                    a = fmaf(wreg[4*q+1], r.y, a);
                    a = fmaf(wreg[4*q+2], r.z, a);
                    a = fmaf(wreg[4*q+3], r.w, a);
                }
                acc[v] = a;
            }
            __syncthreads();
        }

        #pragma unroll
        for (int v = 0; v < VB; v++){
            int ob = s_out[v];
            if (ob < 0) continue;
            float val = acc[v];
            if (ident) val += ident[ob*COUT + tid];
            if (identx){
                int b = ob / Dout3, sp = ob - b*Dout3;
                const float* xp = identx + b*3*Dout3 + sp;
                val = fmaf(identw[tid],          xp[0],       val);
                val = fmaf(identw[COUT + tid],   xp[Dout3],   val);
                val = fmaf(identw[2*COUT + tid], xp[2*Dout3], val);
            }
            out[ob*COUT + tid] = lrelu(val);
        }
        __syncthreads();
    }
}

// ---------------- tensor conv via mma.sync (bf16 hi/lo split) ----------------
// 256 threads (8 warps). Tile: 128 cout (warp w owns rows w*16..w*16+15) x
// 128 voxels. SMEM matrices row pitch 144B. Double-buffered cp.async staging.
template<int CIN, int COUT>
__global__ void __launch_bounds__(256) convt_k(
    const __nv_bfloat16* __restrict__ inh, const __nv_bfloat16* __restrict__ inl,
    const __nv_bfloat16* __restrict__ wh,  const __nv_bfloat16* __restrict__ wl,
    const float* __restrict__ in_mask,
    const int* __restrict__ list, const int* __restrict__ cnt,
    int Din, int Dout, int stride,
    const float* __restrict__ ident,
    float* __restrict__ out)
{
    constexpr int CHUNKS = CIN/64;
    constexpr int NV = 128;
    constexpr int PITCH = 144;                  // bytes per 64-bf16 row
    constexpr int MATB = 128*PITCH;             // 18432 B per matrix

    extern __shared__ char dsm[];               // [2 buf][4 mats][MATB]
    __shared__ int s_tap[27];
    __shared__ int s_ntap;
    __shared__ int s_base[27][NV];
    __shared__ int s_out[NV];

    const int tid  = threadIdx.x;
    const int w    = tid >> 5, lane = tid & 31;
    const int ybase = blockIdx.y * 128;
    const int Din3  = Din*Din*Din;
    const int Dout3 = Dout*Dout*Dout;
    const int n     = list ? *cnt : NB*Dout3;

    const int g  = lane >> 2;                   // groupID
    const int t4 = lane & 3;                    // threadID in group

    for (int vbase = blockIdx.x*NV; vbase < n; vbase += gridDim.x*NV){
        {
            int vi = vbase + tid;
            if (tid < NV){
                int ob = -1;
                if (vi < n){
                    int id = list ? list[vi] : vi;
                    int vx = id % Dout; id /= Dout;
                    int vy = id % Dout; id /= Dout;
                    int vz = id % Dout; int vb = id / Dout;
                    ob = vb*Dout3 + (vz*Dout + vy)*Dout + vx;
                }
                s_out[tid] = ob;
            }
        }
        if (tid == 0) s_ntap = 0;
        __syncthreads();

        // tap table (threads 0..127 handle voxel tid)
        for (int t = 0; t < 27; t++){
            int base = -1;
            if (tid < NV && s_out[tid] >= 0){
                int id = list ? list[vbase + tid] : (vbase + tid);
                int vx = id % Dout; id /= Dout;
                int vy = id % Dout; id /= Dout;
                int vz = id % Dout; int vb = id / Dout;
                int kz = t/9, ky = (t/3)%3, kx = t%3;
                int iz = vz*stride - 1 + kz;
                int iy = vy*stride - 1 + ky;
                int ix = vx*stride - 1 + kx;
                if ((unsigned)iz < (unsigned)Din && (unsigned)iy < (unsigned)Din &&
                    (unsigned)ix < (unsigned)Din){
                    int sp = (iz*Din + iy)*Din + ix;
                    if (!in_mask || in_mask[vb*Din3 + sp] != 0.f)
                        base = (vb*Din3 + sp)*CIN;
                }
            }
            if (tid < NV) s_base[t][tid] = base;
            int any = __syncthreads_or(base >= 0);
            if (any && tid == 0) s_tap[s_ntap++] = t;
        }
        __syncthreads();
        const int ntap = s_ntap;
        const int nit  = ntap * CHUNKS;

        float acc[16][4];
        #pragma unroll
        for (int nt = 0; nt < 16; nt++)
            #pragma unroll
            for (int e = 0; e < 4; e++) acc[nt][e] = 0.f;

        auto issue = [&](int it, int buf){
            int tap = s_tap[it/CHUNKS];
            int ch  = it%CHUNKS;
            char* Ah = dsm + buf*4*MATB;
            char* Al = Ah + MATB;
            char* Bh = Ah + 2*MATB;
            char* Bl = Ah + 3*MATB;
            const __nv_bfloat16* wsrcH = wh + (size_t)((tap*CHUNKS + ch)*COUT + ybase)*64;
            const __nv_bfloat16* wsrcL = wl + (size_t)((tap*CHUNKS + ch)*COUT + ybase)*64;
            #pragma unroll
            for (int j = 0; j < 4; j++){
                int idx = tid*4 + j;
                int row = idx >> 3, col = idx & 7;
                unsigned off = row*PITCH + col*16;
                asm volatile("cp.async.ca.shared.global [%0], [%1], 16;\n"
                    :: "r"(sm_addr(Ah) + off), "l"(wsrcH + row*64 + col*8));
                asm volatile("cp.async.ca.shared.global [%0], [%1], 16;\n"
                    :: "r"(sm_addr(Al) + off), "l"(wsrcL + row*64 + col*8));
                int base = s_base[tap][row];
                const __nv_bfloat16* bsrcH = (base >= 0) ? (inh + base + ch*64 + col*8) : inh;
                const __nv_bfloat16* bsrcL = (base >= 0) ? (inl + base + ch*64 + col*8) : inl;
                int sz = (base >= 0) ? 16 : 0;
                asm volatile("cp.async.ca.shared.global [%0], [%1], 16, %2;\n"
                    :: "r"(sm_addr(Bh) + off), "l"(bsrcH), "r"(sz));
                asm volatile("cp.async.ca.shared.global [%0], [%1], 16, %2;\n"
                    :: "r"(sm_addr(Bl) + off), "l"(bsrcL), "r"(sz));
            }
            asm volatile("cp.async.commit_group;\n");
        };

        if (nit > 0) issue(0, 0);
        for (int it = 0; it < nit; it++){
            int buf = it & 1;
            if (it + 1 < nit){
                issue(it + 1, buf ^ 1);
                asm volatile("cp.async.wait_group 1;\n");
            } else {
                asm volatile("cp.async.wait_group 0;\n");
            }
            __syncthreads();
            unsigned Ah = sm_addr(dsm) + buf*4*MATB;
            unsigned Al = Ah + MATB;
            unsigned Bh = Ah + 2*MATB;
            unsigned Bl = Ah + 3*MATB;
            // per-lane ldmatrix addresses
            unsigned arow = (unsigned)(w*16 + (lane & 15))*PITCH + ((lane >> 4)*16);
            unsigned brow0 = (unsigned)(lane & 7)*PITCH + (((lane >> 3) & 1)*16);
            #pragma unroll
            for (int ks = 0; ks < 4; ks++){
                uint32_t ah[4], al[4];
                ldsm_x4(Ah + arow + ks*32, ah[0], ah[1], ah[2], ah[3]);
                ldsm_x4(Al + arow + ks*32, al[0], al[1], al[2], al[3]);
                #pragma unroll
                for (int nt = 0; nt < 16; nt++){
                    unsigned boff = brow0 + (unsigned)nt*8*PITCH + ks*32;
                    uint32_t bh0, bh1, bl0, bl1;
                    ldsm_x2(Bh + boff, bh0, bh1);
                    ldsm_x2(Bl + boff, bl0, bl1);
                    mma_bf16(acc[nt], ah, bh0, bh1);
                    mma_bf16(acc[nt], al, bh0, bh1);
                    mma_bf16(acc[nt], ah, bl0, bl1);
                }
            }
            __syncthreads();
        }

        // epilogue: lane holds D[cout = w*16+g(+8)][vox = nt*8+t4*2(+1)]
        #pragma unroll
        for (int nt = 0; nt < 16; nt++){
            #pragma unroll
            for (int e = 0; e < 4; e++){
                int v  = nt*8 + t4*2 + (e & 1);
                int co = ybase + w*16 + g + ((e >> 1)*8);
                int ob = s_out[v];
                if (ob < 0) continue;
                float val = acc[nt][e];
                if (ident) val += ident[(size_t)ob*COUT + co];
                out[(size_t)ob*COUT + co] = lrelu(val);
            }
        }
        __syncthreads();
    }
}

// ---------------- final pooled reduce ----------------
__global__ void reduce_k(const float* __restrict__ x4, float* __restrict__ out){
    int b  = blockIdx.x;
    int oc = threadIdx.x;
    const float* p = x4 + b*512*128 + oc;
    float s = 0.f, mx = -3.402823466e38f;
    #pragma unroll 8
    for (int sp = 0; sp < 512; sp++){
        float v = p[sp*128];
        s += v; mx = fmaxf(mx, v);
    }
    out[b*256 + oc]       = s * (1.f/512.f);
    out[b*256 + 128 + oc] = mx;
}

// ---------------- launch ----------------
extern "C" void kernel_launch(void* const* d_in, const int* in_sizes, int n_in,
                              void* d_out, int out_size){
    const float* x    = (const float*)d_in[0];
    const float* mask = (const float*)d_in[1];
    float* out = (float*)d_out;

    float *t1,*x1,*xd1,*t2,*x2,*xd2,*t3,*x3,*x4,*m2,*m3;
    int *l1,*l2,*l3,*cnt;
    cudaGetSymbolAddress((void**)&t1 , g_t1 );
    cudaGetSymbolAddress((void**)&x1 , g_x1 );
    cudaGetSymbolAddress((void**)&xd1, g_xd1);
    cudaGetSymbolAddress((void**)&t2 , g_t2 );
    cudaGetSymbolAddress((void**)&x2 , g_x2 );
    cudaGetSymbolAddress((void**)&xd2, g_xd2);
    cudaGetSymbolAddress((void**)&t3 , g_t3 );
    cudaGetSymbolAddress((void**)&x3 , g_x3 );
    cudaGetSymbolAddress((void**)&x4 , g_x4 );
    cudaGetSymbolAddress((void**)&m2 , g_m2 );
    cudaGetSymbolAddress((void**)&m3 , g_m3 );
    cudaGetSymbolAddress((void**)&l1 , g_list1);
    cudaGetSymbolAddress((void**)&l2 , g_list2);
    cudaGetSymbolAddress((void**)&l3 , g_list3);
    cudaGetSymbolAddress((void**)&cnt, g_cnt);

    float *w1ar,*w1br,*w1dr,*wd1r,*wd3r;
    cudaGetSymbolAddress((void**)&w1ar, g_w1a);
    cudaGetSymbolAddress((void**)&w1br, g_w1b);
    cudaGetSymbolAddress((void**)&w1dr, g_w1d);
    cudaGetSymbolAddress((void**)&wd1r, g_wd1);
    cudaGetSymbolAddress((void**)&wd3r, g_wd3);

    __nv_bfloat16 *w2ah,*w2al,*w2bh,*w2bl,*wd2h,*wd2l,*w3ah,*w3al,*w3bh,*w3bl;
    cudaGetSymbolAddress((void**)&w2ah, g_w2a_h); cudaGetSymbolAddress((void**)&w2al, g_w2a_l);
    cudaGetSymbolAddress((void**)&w2bh, g_w2b_h); cudaGetSymbolAddress((void**)&w2bl, g_w2b_l);
    cudaGetSymbolAddress((void**)&wd2h, g_wd2_h); cudaGetSymbolAddress((void**)&wd2l, g_wd2_l);
    cudaGetSymbolAddress((void**)&w3ah, g_w3a_h); cudaGetSymbolAddress((void**)&w3al, g_w3a_l);
    cudaGetSymbolAddress((void**)&w3bh, g_w3b_h); cudaGetSymbolAddress((void**)&w3bl, g_w3b_l);

    __nv_bfloat16 *xd1h,*xd1l,*t2h,*t2l,*x2h,*x2l,*xd2h,*xd2l,*t3h,*t3l;
    cudaGetSymbolAddress((void**)&xd1h, g_xd1h); cudaGetSymbolAddress((void**)&xd1l, g_xd1l);
    cudaGetSymbolAddress((void**)&t2h,  g_t2h ); cudaGetSymbolAddress((void**)&t2l,  g_t2l );
    cudaGetSymbolAddress((void**)&x2h,  g_x2h ); cudaGetSymbolAddress((void**)&x2l,  g_x2l );
    cudaGetSymbolAddress((void**)&xd2h, g_xd2h); cudaGetSymbolAddress((void**)&xd2l, g_xd2l);
    cudaGetSymbolAddress((void**)&t3h,  g_t3h ); cudaGetSymbolAddress((void**)&t3l,  g_t3l );

    RepackArgs ra;
    {
        const float* src[5] = {(const float*)d_in[2], (const float*)d_in[4],
                               (const float*)d_in[3], (const float*)d_in[5],
                               (const float*)d_in[11]};
        float* dst[5] = {w1ar, w1dr, w1br, wd1r, wd3r};
        const int cins[5]  = {3, 3, 64, 64, 256};
        const int couts[5] = {64,64, 64,128, 128};
        const int k3s[5]   = {27, 1, 27, 27, 27};
        int off = 0;
        for (int i = 0; i < 5; i++){
            ra.src[i]=src[i]; ra.dst[i]=dst[i];
            ra.cin[i]=cins[i]; ra.cout[i]=couts[i]; ra.k3[i]=k3s[i];
            ra.start[i]=off; off += cins[i]*couts[i]*k3s[i];
        }
        ra.ntot = off;
    }
    RepackMMA rm;
    {
        const float* src[5] = {(const float*)d_in[6], (const float*)d_in[7],
                               (const float*)d_in[8], (const float*)d_in[9],
                               (const float*)d_in[10]};
        __nv_bfloat16* dh[5] = {w2ah, w2bh, wd2h, w3ah, w3bh};
        __nv_bfloat16* dl[5] = {w2al, w2bl, wd2l, w3al, w3bl};
        const int cins[5]  = {128, 128, 128, 256, 256};
        const int couts[5] = {128, 128, 256, 256, 256};
        int off = 0;
        for (int i = 0; i < 5; i++){
            rm.src[i]=src[i]; rm.dh[i]=dh[i]; rm.dl[i]=dl[i];
            rm.cin[i]=cins[i]; rm.cout[i]=couts[i];
            rm.start[i]=off; off += cins[i]*couts[i]*27;
        }
        rm.ntot = off;
    }

    const int DSM = 2*4*128*144;   // 147456 B
    cudaFuncSetAttribute(convt_k<128,128>, cudaFuncAttributeMaxDynamicSharedMemorySize, DSM);
    cudaFuncSetAttribute(convt_k<128,256>, cudaFuncAttributeMaxDynamicSharedMemorySize, DSM);
    cudaFuncSetAttribute(convt_k<256,256>, cudaFuncAttributeMaxDynamicSharedMemorySize, DSM);

    repack_all_k<<<(ra.ntot + 255)/256, 256>>>(ra);
    repack_mma_k<<<(rm.ntot + 255)/256, 256>>>(rm);
    down_mask_k<<<(NB*32768 + 255)/256, 256>>>(mask, m2, 64, 32);
    fuse_k<<<(NB*262144 + NB*32768 + NB*4096 + 255)/256, 256>>>(mask, m2, m3, l1, l2, cnt);
    build_list_k<<<(NB*4096 + 255)/256, 256>>>(m3, NB*4096, l3, cnt+2);

    // ---- stage 1 + down1 (scalar, sparse) ----
    conv_s_k<3,64,3,8><<<2048,64>>>(x, w1ar, mask, l1, cnt+0, 64, 64, t1);
    convp_k<64,64,16,8><<<4096,64>>>(t1, w1br, mask, l1, cnt+0, 64,64,1,
                                     nullptr, x, w1dr, x1);
    convp_k<64,128,16,8><<<2048,128>>>(x1, wd1r, mask, l2, cnt+1, 64,32,2,
                                       nullptr, nullptr, nullptr, xd1);
    // ---- stage 2 (tensor) ----
    cvt_k<<<2048,256>>>(xd1, xd1h, xd1l, NB*32768*128);
    convt_k<128,128><<<dim3(512,1),256,DSM>>>(xd1h, xd1l, w2ah, w2al, m2,
                                              l2, cnt+1, 32,32,1, nullptr, t2);
    cvt_k<<<2048,256>>>(t2, t2h, t2l, NB*32768*128);
    fill_k<<<2048,256>>>(xd1, m2, x2, 128, NB*32768*128);
    convt_k<128,128><<<dim3(512,1),256,DSM>>>(t2h, t2l, w2bh, w2bl, m2,
                                              l2, cnt+1, 32,32,1, xd1, x2);
    // ---- down2 (tensor, dense, stride 2) ----
    cvt_k<<<2048,256>>>(x2, x2h, x2l, NB*32768*128);
    convt_k<128,256><<<dim3(64,2),256,DSM>>>(x2h, x2l, wd2h, wd2l, nullptr,
                                             nullptr, nullptr, 32,16,2, nullptr, xd2);
    // ---- stage 3 (tensor) ----
    cvt_k<<<1024,256>>>(xd2, xd2h, xd2l, NB*4096*256);
    convt_k<256,256><<<dim3(64,2),256,DSM>>>(xd2h, xd2l, w3ah, w3al, nullptr,
                                             l3, cnt+2, 16,16,1, nullptr, t3);
    cvt_k<<<1024,256>>>(t3, t3h, t3l, NB*4096*256);
    fill_k<<<1024,256>>>(xd2, nullptr, x3, 256, NB*4096*256);
    convt_k<256,256><<<dim3(64,2),256,DSM>>>(t3h, t3l, w3bh, w3bl, m3,
                                             l3, cnt+2, 16,16,1, xd2, x3);
    // ---- down3 (scalar) ----
    convp_k<256,128,16,8><<<128,128>>>(x3, wd3r, nullptr, nullptr, nullptr,
                                       16,8,2, nullptr, nullptr, nullptr, x4);
    reduce_k<<<2,128>>>(x4, out);
}

// round 14
// speedup vs baseline: 2.1585x; 1.0266x over previous
#include <cuda_runtime.h>
#include <cuda_bf16.h>
#include <cstdint>

#define NB 2
#define NEG 0.2f

// ---------------- scratch (__device__ globals; no allocation) ----------------
__device__ float g_t1 [NB*64*64*64*64];
__device__ float g_x1 [NB*64*64*64*64];
__device__ float g_xd1[NB*32*32*32*128];
__device__ float g_x3 [NB*16*16*16*256];
__device__ float g_xd2[NB*16*16*16*256];
__device__ float g_x4 [NB*8*8*8*128];
__device__ float g_m2 [NB*32*32*32];
__device__ float g_m3 [NB*16*16*16];
__device__ int   g_list1[NB*64*64*64];
__device__ int   g_list2[NB*32*32*32];
__device__ int   g_list3[NB*16*16*16];
__device__ int   g_cnt[3];
// fp32 repacked weights (scalar convs): [tap][cin][cout]
__device__ float g_w1a[27*3*64];
__device__ float g_w1b[27*64*64];
__device__ float g_w1d[3*64];
__device__ float g_wd1[27*64*128];
__device__ float g_wd3[27*256*128];
// bf16 hi/lo MMA weights: [tap][chunk64][COUT][64]
__device__ __nv_bfloat16 g_w2a_h[27*2*128*64], g_w2a_l[27*2*128*64];
__device__ __nv_bfloat16 g_w2b_h[27*2*128*64], g_w2b_l[27*2*128*64];
__device__ __nv_bfloat16 g_wd2_h[27*2*256*64], g_wd2_l[27*2*256*64];
__device__ __nv_bfloat16 g_w3a_h[27*4*256*64], g_w3a_l[27*4*256*64];
__device__ __nv_bfloat16 g_w3b_h[27*4*256*64], g_w3b_l[27*4*256*64];
// bf16 hi/lo activations (channel-last)
__device__ __nv_bfloat16 g_xd1h[NB*32768*128], g_xd1l[NB*32768*128];
__device__ __nv_bfloat16 g_t2h [NB*32768*128], g_t2l [NB*32768*128];
__device__ __nv_bfloat16 g_x2h [NB*32768*128], g_x2l [NB*32768*128];
__device__ __nv_bfloat16 g_xd2h[NB*4096*256],  g_xd2l[NB*4096*256];
__device__ __nv_bfloat16 g_t3h [NB*4096*256],  g_t3l [NB*4096*256];

__device__ __forceinline__ float lrelu(float v){ return v >= 0.f ? v : NEG*v; }
__device__ __forceinline__ unsigned sm_addr(const void* p){
    return (unsigned)__cvta_generic_to_shared(p);
}
__device__ __forceinline__ void split_bf16(float v, __nv_bfloat16& h, __nv_bfloat16& l){
    h = __float2bfloat16(v);
    l = __float2bfloat16(v - __bfloat162float(h));
}

// ---------------- mma.sync helpers ----------------
__device__ __forceinline__ void ldsm_x4(uint32_t a, uint32_t& r0, uint32_t& r1,
                                        uint32_t& r2, uint32_t& r3){
    asm volatile("ldmatrix.sync.aligned.m8n8.x4.shared.b16 {%0,%1,%2,%3}, [%4];"
                 : "=r"(r0), "=r"(r1), "=r"(r2), "=r"(r3) : "r"(a));
}
__device__ __forceinline__ void ldsm_x2(uint32_t a, uint32_t& r0, uint32_t& r1){
    asm volatile("ldmatrix.sync.aligned.m8n8.x2.shared.b16 {%0,%1}, [%2];"
                 : "=r"(r0), "=r"(r1) : "r"(a));
}
__device__ __forceinline__ void mma_bf16(float* c, const uint32_t* a,
                                         uint32_t b0, uint32_t b1){
    asm volatile(
        "mma.sync.aligned.m16n8k16.row.col.f32.bf16.bf16.f32 "
        "{%0,%1,%2,%3},{%4,%5,%6,%7},{%8,%9},{%0,%1,%2,%3};"
        : "+f"(c[0]), "+f"(c[1]), "+f"(c[2]), "+f"(c[3])
        : "r"(a[0]), "r"(a[1]), "r"(a[2]), "r"(a[3]), "r"(b0), "r"(b1));
}

// ---------------- setup kernels ----------------
struct RepackArgs {
    const float* src[5];
    float*       dst[5];
    int cin[5], cout[5], k3[5], start[5];
    int ntot;
};
__global__ void repack_all_k(RepackArgs a){
    int idx = blockIdx.x*blockDim.x + threadIdx.x;
    if (idx < 3) g_cnt[idx] = 0;
    if (idx >= a.ntot) return;
    int s = 0;
    #pragma unroll
    for (int k = 1; k < 5; k++) if (idx >= a.start[k]) s = k;
    int i = idx - a.start[s];
    int CIN = a.cin[s], COUT = a.cout[s], K3 = a.k3[s];
    int oc = i / (CIN*K3);
    int r  = i % (CIN*K3);
    int ic = r / K3;
    int k  = r % K3;
    a.dst[s][(k*CIN + ic)*COUT + oc] = a.src[s][i];
}

struct RepackMMA {
    const float* src[5];
    __nv_bfloat16 *dh[5], *dl[5];
    int cin[5], cout[5], start[5];
    int ntot;
};
__global__ void repack_mma_k(RepackMMA a){
    int idx = blockIdx.x*blockDim.x + threadIdx.x;
    if (idx >= a.ntot) return;
    int s = 0;
    #pragma unroll
    for (int k = 1; k < 5; k++) if (idx >= a.start[k]) s = k;
    int i = idx - a.start[s];
    int CIN = a.cin[s], COUT = a.cout[s];
    int oc = i / (CIN*27);
    int r  = i % (CIN*27);
    int ic = r / 27;
    int t  = r % 27;
    float v = a.src[s][i];
    __nv_bfloat16 h, l; split_bf16(v, h, l);
    int di = ((t*(CIN/64) + ic/64)*COUT + oc)*64 + (ic % 64);
    a.dh[s][di] = h;
    a.dl[s][di] = l;
}

__global__ void down_mask_k(const float* __restrict__ in, float* __restrict__ out,
                            int Din, int Dout){
    int i = blockIdx.x*blockDim.x + threadIdx.x;
    int tot = NB*Dout*Dout*Dout;
    if (i >= tot) return;
    int ox = i % Dout, t = i / Dout;
    int oy = t % Dout; t /= Dout;
    int oz = t % Dout; int b = t / Dout;
    float m = 0.f;
    for (int kz = 0; kz < 3; kz++){
        int iz = 2*oz - 1 + kz; if ((unsigned)iz >= (unsigned)Din) continue;
        for (int ky = 0; ky < 3; ky++){
            int iy = 2*oy - 1 + ky; if ((unsigned)iy >= (unsigned)Din) continue;
            for (int kx = 0; kx < 3; kx++){
                int ix = 2*ox - 1 + kx; if ((unsigned)ix >= (unsigned)Din) continue;
                m = fmaxf(m, in[((b*Din + iz)*Din + iy)*Din + ix]);
            }
        }
    }
    out[i] = m;
}

__global__ void fuse_k(const float* __restrict__ mask, const float* __restrict__ m2,
                       float* __restrict__ m3, int* __restrict__ l1,
                       int* __restrict__ l2, int* __restrict__ cnt){
    const int A = NB*262144, B = NB*32768, C = NB*4096;
    int idx = blockIdx.x*blockDim.x + threadIdx.x;
    if (idx < A){
        if (mask[idx] != 0.f){ int p = atomicAdd(cnt+0, 1); l1[p] = idx; }
    } else if (idx < A+B){
        int i = idx - A;
        if (m2[i] != 0.f){ int p = atomicAdd(cnt+1, 1); l2[p] = i; }
    } else if (idx < A+B+C){
        int i = idx - A - B;
        int ox = i % 16, t = i / 16;
        int oy = t % 16; t /= 16;
        int oz = t % 16; int b = t / 16;
        float m = 0.f;
        for (int kz = 0; kz < 3; kz++){
            int iz = 2*oz - 1 + kz; if ((unsigned)iz >= 32u) continue;
            for (int ky = 0; ky < 3; ky++){
                int iy = 2*oy - 1 + ky; if ((unsigned)iy >= 32u) continue;
                for (int kx = 0; kx < 3; kx++){
                    int ix = 2*ox - 1 + kx; if ((unsigned)ix >= 32u) continue;
                    m = fmaxf(m, m2[((b*32 + iz)*32 + iy)*32 + ix]);
                }
            }
        }
        m3[i] = m;
    }
}

__global__ void build_list_k(const float* __restrict__ m, int tot,
                             int* __restrict__ list, int* __restrict__ cnt){
    int i = blockIdx.x*blockDim.x + threadIdx.x;
    if (i < tot && m[i] != 0.f){
        int p = atomicAdd(cnt, 1);
        list[p] = i;
    }
}

// out fp32 (nullable) / outh+outl bf16 (nullable) = masked lrelu(in)
__global__ void fill_k(const float* __restrict__ in, const float* __restrict__ m,
                       float* __restrict__ out,
                       __nv_bfloat16* __restrict__ outh,
                       __nv_bfloat16* __restrict__ outl, int C, int n){
    int i  = blockIdx.x*blockDim.x + threadIdx.x;
    int st = gridDim.x*blockDim.x;
    for (int j = i; j < n; j += st){
        float v = in[j];
        float r = lrelu(v);
        if (m && m[j/C] == 0.f) r = 0.f;
        if (out) out[j] = r;
        if (outh){
            __nv_bfloat16 h, l; split_bf16(r, h, l);
            outh[j] = h; outl[j] = l;
        }
    }
}

// ---------------- simple conv (stage-1a: CIN=3, NCDHW in) ----------------
template<int CIN, int COUT, int CINC, int VB>
__global__ void __launch_bounds__(COUT) conv_s_k(
    const float* __restrict__ in, const float* __restrict__ wr,
    const float* __restrict__ in_mask,
    const int* __restrict__ list, const int* __restrict__ cnt,
    int Din, int Dout,
    float* __restrict__ out)
{
    __shared__ int s_base[VB];
    __shared__ int s_out [VB];
    __shared__ float s_in[VB][CINC];

    const int tid   = threadIdx.x;
    const int Din3  = Din*Din*Din;
    const int Dout3 = Dout*Dout*Dout;
    const int n     = *cnt;

    for (int vbase = blockIdx.x*VB; vbase < n; vbase += gridDim.x*VB){
        int vb=0,vz=0,vy=0,vx=0,vvalid=0;
        if (tid < VB){
            int vi = vbase + tid;
            int ob = -1;
            if (vi < n){
                int id = list[vi];
                vx = id % Dout; id /= Dout;
                vy = id % Dout; id /= Dout;
                vz = id % Dout; vb = id / Dout;
                ob = vb*Dout3 + (vz*Dout + vy)*Dout + vx;
                vvalid = 1;
            }
            s_out[tid] = ob;
        }
        __syncthreads();

        float acc[VB];
        #pragma unroll
        for (int v = 0; v < VB; v++) acc[v] = 0.f;

        for (int t = 0; t < 27; t++){
            int pred = 0;
            if (tid < VB){
                int base = -1;
                if (vvalid){
                    int kz = t/9, ky = (t/3)%3, kx = t%3;
                    int iz = vz - 1 + kz, iy = vy - 1 + ky, ix = vx - 1 + kx;
                    if ((unsigned)iz < (unsigned)Din && (unsigned)iy < (unsigned)Din &&
                        (unsigned)ix < (unsigned)Din){
                        int sp = (iz*Din + iy)*Din + ix;
                        if (in_mask[vb*Din3 + sp] != 0.f)
                            base = vb*CIN*Din3 + sp;
                    }
                }
                s_base[tid] = base;
                pred = (base >= 0);
            }
            if (!__syncthreads_or(pred)) continue;

            float wreg[CINC];
            #pragma unroll
            for (int c = 0; c < CINC; c++)
                wreg[c] = wr[(t*CIN + c)*COUT + tid];
            #pragma unroll 1
            for (int i = tid; i < CINC*VB; i += COUT){
                int v = i / CINC, c = i % CINC;
                int base = s_base[v];
                s_in[v][c] = (base >= 0) ? in[base + c*Din3] : 0.f;
            }
            __syncthreads();
            #pragma unroll
            for (int v = 0; v < VB; v++){
                float a = acc[v];
                #pragma unroll
                for (int c = 0; c < CINC; c++)
                    a = fmaf(wreg[c], s_in[v][c], a);
                acc[v] = a;
            }
            __syncthreads();
        }

        #pragma unroll
        for (int v = 0; v < VB; v++){
            int ob = s_out[v];
            if (ob < 0) continue;
            out[ob*COUT + tid] = lrelu(acc[v]);
        }
        __syncthreads();
    }
}

// ---------------- scalar pipelined conv (sparse stages) ----------------
template<int CIN, int COUT, int CINC, int VB>
__global__ void __launch_bounds__(COUT) convp_k(
    const float* __restrict__ in, const float* __restrict__ wr,
    const float* __restrict__ in_mask,
    const int* __restrict__ list, const int* __restrict__ cnt,
    int Din, int Dout, int stride,
    const float* __restrict__ ident,
    const float* __restrict__ identx, const float* __restrict__ identw,
    float* __restrict__ out,
    __nv_bfloat16* __restrict__ outh, __nv_bfloat16* __restrict__ outl)
{
    constexpr int CHUNKS = CIN/CINC;
    constexpr int F4 = VB*CINC/4;
    constexpr int PT = (F4 + COUT - 1)/COUT;
    __shared__ int s_tap[27];
    __shared__ int s_ntap;
    __shared__ int s_base[27][VB];
    __shared__ int s_out[VB];
    __shared__ __align__(16) float4 s_in[2][F4];

    const int tid   = threadIdx.x;
    const int Din3  = Din*Din*Din;
    const int Dout3 = Dout*Dout*Dout;
    const int n     = list ? *cnt : NB*Dout3;

    for (int vbase = blockIdx.x*VB; vbase < n; vbase += gridDim.x*VB){
        int vb=0,vz=0,vy=0,vx=0,vvalid=0;
        if (tid < VB){
            int vi = vbase + tid;
            int ob = -1;
            if (vi < n){
                int id = list ? list[vi] : vi;
                vx = id % Dout; id /= Dout;
                vy = id % Dout; id /= Dout;
                vz = id % Dout; vb = id / Dout;
                ob = vb*Dout3 + (vz*Dout + vy)*Dout + vx;
                vvalid = 1;
            }
            s_out[tid] = ob;
        }
        if (tid == 0) s_ntap = 0;
        __syncthreads();

        for (int t = 0; t < 27; t++){
            int pred = 0;
            if (tid < VB){
                int base = -1;
                if (vvalid){
                    int kz = t/9, ky = (t/3)%3, kx = t%3;
                    int iz = vz*stride - 1 + kz;
                    int iy = vy*stride - 1 + ky;
                    int ix = vx*stride - 1 + kx;
                    if ((unsigned)iz < (unsigned)Din && (unsigned)iy < (unsigned)Din &&
                        (unsigned)ix < (unsigned)Din){
                        int sp = (iz*Din + iy)*Din + ix;
                        if (!in_mask || in_mask[vb*Din3 + sp] != 0.f)
                            base = (vb*Din3 + sp)*CIN;
                    }
                }
                s_base[t][tid] = base;
                pred = (base >= 0);
            }
            int any = __syncthreads_or(pred);
            if (any && tid == 0) s_tap[s_ntap++] = t;
        }
        __syncthreads();
        const int ntap = s_ntap;
        const int nit  = ntap * CHUNKS;

        float acc[VB];
        #pragma unroll
        for (int v = 0; v < VB; v++) acc[v] = 0.f;

        auto issue = [&](int it, int buf){
            int tap = s_tap[it/CHUNKS];
            int cc  = (it%CHUNKS)*CINC;
            #pragma unroll
            for (int k = 0; k < PT; k++){
                int j = tid + k*COUT;
                if ((F4 % COUT == 0) || (j < F4)){
                    int v = j/(CINC/4), c4 = j%(CINC/4);
                    int base = s_base[tap][v];
                    const float* src = (base >= 0) ? (in + base + cc + c4*4) : in;
                    int sz = (base >= 0) ? 16 : 0;
                    unsigned dst = sm_addr(&s_in[buf][j]);
                    asm volatile("cp.async.ca.shared.global [%0], [%1], 16, %2;\n"
                                 :: "r"(dst), "l"(src), "r"(sz));
                }
            }
            asm volatile("cp.async.commit_group;\n");
        };

        if (nit > 0) issue(0, 0);
        for (int it = 0; it < nit; it++){
            int buf = it & 1;
            int tap = s_tap[it/CHUNKS];
            int cc  = (it%CHUNKS)*CINC;
            float wreg[CINC];
            #pragma unroll
            for (int c = 0; c < CINC; c++)
                wreg[c] = wr[(tap*CIN + cc + c)*COUT + tid];
            if (it + 1 < nit){
                issue(it + 1, buf ^ 1);
                asm volatile("cp.async.wait_group 1;\n");
            } else {
                asm volatile("cp.async.wait_group 0;\n");
            }
            __syncthreads();
            const float4* rows = s_in[buf];
            #pragma unroll
            for (int v = 0; v < VB; v++){
                float a = acc[v];
                #pragma unroll
                for (int q = 0; q < CINC/4; q++){
                    float4 r = rows[v*(CINC/4) + q];
                    a = fmaf(wreg[4*q+0], r.x, a);
                    a = fmaf(wreg[4*q+1], r.y, a);
                    a = fmaf(wreg[4*q+2], r.z, a);
                    a = fmaf(wreg[4*q+3], r.w, a);
                }
                acc[v] = a;
            }
            __syncthreads();
        }

        #pragma unroll
        for (int v = 0; v < VB; v++){
            int ob = s_out[v];
            if (ob < 0) continue;
            float val = acc[v];
            if (ident) val += ident[ob*COUT + tid];
            if (identx){
                int b = ob / Dout3, sp = ob - b*Dout3;
                const float* xp = identx + b*3*Dout3 + sp;
                val = fmaf(identw[tid],          xp[0],       val);
                val = fmaf(identw[COUT + tid],   xp[Dout3],   val);
                val = fmaf(identw[2*COUT + tid], xp[2*Dout3], val);
            }
            val = lrelu(val);
            if (out) out[ob*COUT + tid] = val;
            if (outh){
                __nv_bfloat16 h, l; split_bf16(val, h, l);
                outh[ob*COUT + tid] = h;
                outl[ob*COUT + tid] = l;
            }
        }
        __syncthreads();
    }
}

// ---------------- tensor conv via mma.sync (bf16 hi/lo split) ----------------
// 256 threads = 8 warps, 2D tiled: warp (wm,wn) owns 32 cout x 64 vox.
// Tile: 128 cout x 128 vox, K-chunk 64, 3 combos (AhBh+AlBh+AhBl).
template<int CIN, int COUT>
__global__ void __launch_bounds__(256) convt_k(
    const __nv_bfloat16* __restrict__ inh, const __nv_bfloat16* __restrict__ inl,
    const __nv_bfloat16* __restrict__ wh,  const __nv_bfloat16* __restrict__ wl,
    const float* __restrict__ in_mask,
    const int* __restrict__ list, const int* __restrict__ cnt,
    int Din, int Dout, int stride,
    const float* __restrict__ ident,
    float* __restrict__ out,
    __nv_bfloat16* __restrict__ outh, __nv_bfloat16* __restrict__ outl)
{
    constexpr int CHUNKS = CIN/64;
    constexpr int NV = 128;
    constexpr int PITCH = 144;
    constexpr int MATB = 128*PITCH;

    extern __shared__ char dsm[];
    __shared__ int s_tap[27];
    __shared__ int s_ntap;
    __shared__ int s_base[27][NV];
    __shared__ int s_out[NV];

    const int tid  = threadIdx.x;
    const int w    = tid >> 5, lane = tid & 31;
    const int wm   = w & 3, wn = w >> 2;
    const int ybase = blockIdx.y * 128;
    const int Din3  = Din*Din*Din;
    const int Dout3 = Dout*Dout*Dout;
    const int n     = list ? *cnt : NB*Dout3;

    const int g  = lane >> 2;
    const int t4 = lane & 3;

    for (int vbase = blockIdx.x*NV; vbase < n; vbase += gridDim.x*NV){
        if (tid < NV){
            int vi = vbase + tid;
            int ob = -1;
            if (vi < n){
                int id = list ? list[vi] : vi;
                int vx = id % Dout; id /= Dout;
                int vy = id % Dout; id /= Dout;
                int vz = id % Dout; int vb = id / Dout;
                ob = vb*Dout3 + (vz*Dout + vy)*Dout + vx;
            }
            s_out[tid] = ob;
        }
        if (tid == 0) s_ntap = 0;
        __syncthreads();

        for (int t = 0; t < 27; t++){
            int base = -1;
            if (tid < NV && s_out[tid] >= 0){
                int id = list ? list[vbase + tid] : (vbase + tid);
                int vx = id % Dout; id /= Dout;
                int vy = id % Dout; id /= Dout;
                int vz = id % Dout; int vb = id / Dout;
                int kz = t/9, ky = (t/3)%3, kx = t%3;
                int iz = vz*stride - 1 + kz;
                int iy = vy*stride - 1 + ky;
                int ix = vx*stride - 1 + kx;
                if ((unsigned)iz < (unsigned)Din && (unsigned)iy < (unsigned)Din &&
                    (unsigned)ix < (unsigned)Din){
                    int sp = (iz*Din + iy)*Din + ix;
                    if (!in_mask || in_mask[vb*Din3 + sp] != 0.f)
                        base = (vb*Din3 + sp)*CIN;
                }
            }
            if (tid < NV) s_base[t][tid] = base;
            int any = __syncthreads_or(base >= 0);
            if (any && tid == 0) s_tap[s_ntap++] = t;
        }
        __syncthreads();
        const int ntap = s_ntap;
        const int nit  = ntap * CHUNKS;

        float acc[2][8][4];
        #pragma unroll
        for (int mi = 0; mi < 2; mi++)
            #pragma unroll
            for (int nt = 0; nt < 8; nt++)
                #pragma unroll
                for (int e = 0; e < 4; e++) acc[mi][nt][e] = 0.f;

        auto issue = [&](int it, int buf){
            int tap = s_tap[it/CHUNKS];
            int ch  = it%CHUNKS;
            char* Ah = dsm + buf*4*MATB;
            char* Al = Ah + MATB;
            char* Bh = Ah + 2*MATB;
            char* Bl = Ah + 3*MATB;
            const __nv_bfloat16* wsrcH = wh + (size_t)((tap*CHUNKS + ch)*COUT + ybase)*64;
            const __nv_bfloat16* wsrcL = wl + (size_t)((tap*CHUNKS + ch)*COUT + ybase)*64;
            #pragma unroll
            for (int j = 0; j < 4; j++){
                int idx = tid*4 + j;
                int row = idx >> 3, col = idx & 7;
                unsigned off = row*PITCH + col*16;
                asm volatile("cp.async.ca.shared.global [%0], [%1], 16;\n"
                    :: "r"(sm_addr(Ah) + off), "l"(wsrcH + row*64 + col*8));
                asm volatile("cp.async.ca.shared.global [%0], [%1], 16;\n"
                    :: "r"(sm_addr(Al) + off), "l"(wsrcL + row*64 + col*8));
                int base = s_base[tap][row];
                const __nv_bfloat16* bsrcH = (base >= 0) ? (inh + base + ch*64 + col*8) : inh;
                const __nv_bfloat16* bsrcL = (base >= 0) ? (inl + base + ch*64 + col*8) : inl;
                int sz = (base >= 0) ? 16 : 0;
                asm volatile("cp.async.ca.shared.global [%0], [%1], 16, %2;\n"
                    :: "r"(sm_addr(Bh) + off), "l"(bsrcH), "r"(sz));
                asm volatile("cp.async.ca.shared.global [%0], [%1], 16, %2;\n"
                    :: "r"(sm_addr(Bl) + off), "l"(bsrcL), "r"(sz));
            }
            asm volatile("cp.async.commit_group;\n");
        };

        if (nit > 0) issue(0, 0);
        for (int it = 0; it < nit; it++){
            int buf = it & 1;
            if (it + 1 < nit){
                issue(it + 1, buf ^ 1);
                asm volatile("cp.async.wait_group 1;\n");
            } else {
                asm volatile("cp.async.wait_group 0;\n");
            }
            __syncthreads();
            unsigned Ah = sm_addr(dsm) + buf*4*MATB;
            unsigned Al = Ah + MATB;
            unsigned Bh = Ah + 2*MATB;
            unsigned Bl = Ah + 3*MATB;
            unsigned arow0 = (unsigned)(wm*32 + (lane & 15))*PITCH + ((lane >> 4)*16);
            unsigned brow0 = (unsigned)(wn*64 + (lane & 7))*PITCH + (((lane >> 3) & 1)*16);
            #pragma unroll
            for (int ks = 0; ks < 4; ks++){
                uint32_t ah[2][4], al[2][4];
                #pragma unroll
                for (int mi = 0; mi < 2; mi++){
                    ldsm_x4(Ah + arow0 + mi*16*PITCH + ks*32,
                            ah[mi][0], ah[mi][1], ah[mi][2], ah[mi][3]);
                    ldsm_x4(Al + arow0 + mi*16*PITCH + ks*32,
                            al[mi][0], al[mi][1], al[mi][2], al[mi][3]);
                }
                #pragma unroll
                for (int nt = 0; nt < 8; nt++){
                    unsigned boff = brow0 + (unsigned)nt*8*PITCH + ks*32;
                    uint32_t bh0, bh1, bl0, bl1;
                    ldsm_x2(Bh + boff, bh0, bh1);
                    ldsm_x2(Bl + boff, bl0, bl1);
                    #pragma unroll
                    for (int mi = 0; mi < 2; mi++){
                        mma_bf16(acc[mi][nt], ah[mi], bh0, bh1);
                        mma_bf16(acc[mi][nt], al[mi], bh0, bh1);
                        mma_bf16(acc[mi][nt], ah[mi], bl0, bl1);
                    }
                }
            }
            __syncthreads();
        }

        // epilogue: lane holds D[cout=wm*32+mi*16+g(+8)][vox=wn*64+nt*8+t4*2(+1)]
        #pragma unroll
        for (int mi = 0; mi < 2; mi++){
            #pragma unroll
            for (int nt = 0; nt < 8; nt++){
                #pragma unroll
                for (int e = 0; e < 4; e++){
                    int v  = wn*64 + nt*8 + t4*2 + (e & 1);
                    int co = ybase + wm*32 + mi*16 + g + ((e >> 1)*8);
                    int ob = s_out[v];
                    if (ob < 0) continue;
                    float val = acc[mi][nt][e];
                    if (ident) val += ident[(size_t)ob*COUT + co];
                    val = lrelu(val);
                    size_t oi = (size_t)ob*COUT + co;
                    if (out) out[oi] = val;
                    if (outh){
                        __nv_bfloat16 h, l; split_bf16(val, h, l);
                        outh[oi] = h; outl[oi] = l;
                    }
                }
            }
        }
        __syncthreads();
    }
}

// ---------------- final pooled reduce ----------------
__global__ void reduce_k(const float* __restrict__ x4, float* __restrict__ out){
    int b  = blockIdx.x;
    int oc = threadIdx.x;
    const float* p = x4 + b*512*128 + oc;
    float s = 0.f, mx = -3.402823466e38f;
    #pragma unroll 8
    for (int sp = 0; sp < 512; sp++){
        float v = p[sp*128];
        s += v; mx = fmaxf(mx, v);
    }
    out[b*256 + oc]       = s * (1.f/512.f);
    out[b*256 + 128 + oc] = mx;
}

// ---------------- launch ----------------
extern "C" void kernel_launch(void* const* d_in, const int* in_sizes, int n_in,
                              void* d_out, int out_size){
    const float* x    = (const float*)d_in[0];
    const float* mask = (const float*)d_in[1];
    float* out = (float*)d_out;

    float *t1,*x1,*xd1,*x3,*xd2,*x4,*m2,*m3;
    int *l1,*l2,*l3,*cnt;
    cudaGetSymbolAddress((void**)&t1 , g_t1 );
    cudaGetSymbolAddress((void**)&x1 , g_x1 );
    cudaGetSymbolAddress((void**)&xd1, g_xd1);
    cudaGetSymbolAddress((void**)&x3 , g_x3 );
    cudaGetSymbolAddress((void**)&xd2, g_xd2);
    cudaGetSymbolAddress((void**)&x4 , g_x4 );
    cudaGetSymbolAddress((void**)&m2 , g_m2 );
    cudaGetSymbolAddress((void**)&m3 , g_m3 );
    cudaGetSymbolAddress((void**)&l1 , g_list1);
    cudaGetSymbolAddress((void**)&l2 , g_list2);
    cudaGetSymbolAddress((void**)&l3 , g_list3);
    cudaGetSymbolAddress((void**)&cnt, g_cnt);

    float *w1ar,*w1br,*w1dr,*wd1r,*wd3r;
    cudaGetSymbolAddress((void**)&w1ar, g_w1a);
    cudaGetSymbolAddress((void**)&w1br, g_w1b);
    cudaGetSymbolAddress((void**)&w1dr, g_w1d);
    cudaGetSymbolAddress((void**)&wd1r, g_wd1);
    cudaGetSymbolAddress((void**)&wd3r, g_wd3);

    __nv_bfloat16 *w2ah,*w2al,*w2bh,*w2bl,*wd2h,*wd2l,*w3ah,*w3al,*w3bh,*w3bl;
    cudaGetSymbolAddress((void**)&w2ah, g_w2a_h); cudaGetSymbolAddress((void**)&w2al, g_w2a_l);
    cudaGetSymbolAddress((void**)&w2bh, g_w2b_h); cudaGetSymbolAddress((void**)&w2bl, g_w2b_l);
    cudaGetSymbolAddress((void**)&wd2h, g_wd2_h); cudaGetSymbolAddress((void**)&wd2l, g_wd2_l);
    cudaGetSymbolAddress((void**)&w3ah, g_w3a_h); cudaGetSymbolAddress((void**)&w3al, g_w3a_l);
    cudaGetSymbolAddress((void**)&w3bh, g_w3b_h); cudaGetSymbolAddress((void**)&w3bl, g_w3b_l);

    __nv_bfloat16 *xd1h,*xd1l,*t2h,*t2l,*x2h,*x2l,*xd2h,*xd2l,*t3h,*t3l;
    cudaGetSymbolAddress((void**)&xd1h, g_xd1h); cudaGetSymbolAddress((void**)&xd1l, g_xd1l);
    cudaGetSymbolAddress((void**)&t2h,  g_t2h ); cudaGetSymbolAddress((void**)&t2l,  g_t2l );
    cudaGetSymbolAddress((void**)&x2h,  g_x2h ); cudaGetSymbolAddress((void**)&x2l,  g_x2l );
    cudaGetSymbolAddress((void**)&xd2h, g_xd2h); cudaGetSymbolAddress((void**)&xd2l, g_xd2l);
    cudaGetSymbolAddress((void**)&t3h,  g_t3h ); cudaGetSymbolAddress((void**)&t3l,  g_t3l );

    RepackArgs ra;
    {
        const float* src[5] = {(const float*)d_in[2], (const float*)d_in[4],
                               (const float*)d_in[3], (const float*)d_in[5],
                               (const float*)d_in[11]};
        float* dst[5] = {w1ar, w1dr, w1br, wd1r, wd3r};
        const int cins[5]  = {3, 3, 64, 64, 256};
        const int couts[5] = {64,64, 64,128, 128};
        const int k3s[5]   = {27, 1, 27, 27, 27};
        int off = 0;
        for (int i = 0; i < 5; i++){
            ra.src[i]=src[i]; ra.dst[i]=dst[i];
            ra.cin[i]=cins[i]; ra.cout[i]=couts[i]; ra.k3[i]=k3s[i];
            ra.start[i]=off; off += cins[i]*couts[i]*k3s[i];
        }
        ra.ntot = off;
    }
    RepackMMA rm;
    {
        const float* src[5] = {(const float*)d_in[6], (const float*)d_in[7],
                               (const float*)d_in[8], (const float*)d_in[9],
                               (const float*)d_in[10]};
        __nv_bfloat16* dh[5] = {w2ah, w2bh, wd2h, w3ah, w3bh};
        __nv_bfloat16* dl[5] = {w2al, w2bl, wd2l, w3al, w3bl};
        const int cins[5]  = {128, 128, 128, 256, 256};
        const int couts[5] = {128, 128, 256, 256, 256};
        int off = 0;
        for (int i = 0; i < 5; i++){
            rm.src[i]=src[i]; rm.dh[i]=dh[i]; rm.dl[i]=dl[i];
            rm.cin[i]=cins[i]; rm.cout[i]=couts[i];
            rm.start[i]=off; off += cins[i]*couts[i]*27;
        }
        rm.ntot = off;
    }

    const int DSM = 2*4*128*144;   // 147456 B
    cudaFuncSetAttribute(convt_k<128,128>, cudaFuncAttributeMaxDynamicSharedMemorySize, DSM);
    cudaFuncSetAttribute(convt_k<128,256>, cudaFuncAttributeMaxDynamicSharedMemorySize, DSM);
    cudaFuncSetAttribute(convt_k<256,256>, cudaFuncAttributeMaxDynamicSharedMemorySize, DSM);

    repack_all_k<<<(ra.ntot + 255)/256, 256>>>(ra);
    repack_mma_k<<<(rm.ntot + 255)/256, 256>>>(rm);
    down_mask_k<<<(NB*32768 + 255)/256, 256>>>(mask, m2, 64, 32);
    fuse_k<<<(NB*262144 + NB*32768 + NB*4096 + 255)/256, 256>>>(mask, m2, m3, l1, l2, cnt);
    build_list_k<<<(NB*4096 + 255)/256, 256>>>(m3, NB*4096, l3, cnt+2);

    // ---- stage 1 + down1 (scalar, sparse); down1 emits bf16 hi/lo fused ----
    conv_s_k<3,64,3,8><<<2048,64>>>(x, w1ar, mask, l1, cnt+0, 64, 64, t1);
    convp_k<64,64,16,8><<<4096,64>>>(t1, w1br, mask, l1, cnt+0, 64,64,1,
                                     nullptr, x, w1dr, x1, nullptr, nullptr);
    convp_k<64,128,16,8><<<2048,128>>>(x1, wd1r, mask, l2, cnt+1, 64,32,2,
                                       nullptr, nullptr, nullptr, xd1, xd1h, xd1l);
    // ---- stage 2 (tensor; bf16 outputs fused, fp32 skipped where unused) ----
    convt_k<128,128><<<dim3(512,1),256,DSM>>>(xd1h, xd1l, w2ah, w2al, m2,
                                              l2, cnt+1, 32,32,1, nullptr,
                                              nullptr, t2h, t2l);
    fill_k<<<2048,256>>>(xd1, m2, nullptr, x2h, x2l, 128, NB*32768*128);
    convt_k<128,128><<<dim3(512,1),256,DSM>>>(t2h, t2l, w2bh, w2bl, m2,
                                              l2, cnt+1, 32,32,1, xd1,
                                              nullptr, x2h, x2l);
    // ---- down2 (tensor, dense, stride 2; fp32 needed as stage-3b ident) ----
    convt_k<128,256><<<dim3(64,2),256,DSM>>>(x2h, x2l, wd2h, wd2l, nullptr,
                                             nullptr, nullptr, 32,16,2, nullptr,
                                             xd2, xd2h, xd2l);
    // ---- stage 3 (tensor) ----
    convt_k<256,256><<<dim3(64,2),256,DSM>>>(xd2h, xd2l, w3ah, w3al, nullptr,
                                             l3, cnt+2, 16,16,1, nullptr,
                                             nullptr, t3h, t3l);
    fill_k<<<1024,256>>>(xd2, nullptr, x3, nullptr, nullptr, 256, NB*4096*256);
    convt_k<256,256><<<dim3(64,2),256,DSM>>>(t3h, t3l, w3bh, w3bl, m3,
                                             l3, cnt+2, 16,16,1, xd2,
                                             x3, nullptr, nullptr);
    // ---- down3 (scalar) ----
    convp_k<256,128,16,8><<<128,128>>>(x3, wd3r, nullptr, nullptr, nullptr,
                                       16,8,2, nullptr, nullptr, nullptr,
                                       x4, nullptr, nullptr);
    reduce_k<<<2,128>>>(x4, out);
}

// round 15
// speedup vs baseline: 2.1623x; 1.0018x over previous
#include <cuda_runtime.h>
#include <cuda_bf16.h>
#include <cstdint>

#define NB 2
#define NEG 0.2f

// ---------------- scratch (__device__ globals; no allocation) ----------------
__device__ float g_t1 [NB*64*64*64*64];
__device__ float g_x1 [NB*64*64*64*64];
__device__ float g_xd1[NB*32*32*32*128];
__device__ float g_x3 [NB*16*16*16*256];
__device__ float g_xd2[NB*16*16*16*256];
__device__ float g_x4 [NB*8*8*8*128];
__device__ float g_m2 [NB*32*32*32];
__device__ float g_m3 [NB*16*16*16];
__device__ int   g_list1[NB*64*64*64];
__device__ int   g_list2[NB*32*32*32];
__device__ int   g_list3[NB*16*16*16];
__device__ int   g_cnt[3];
// fp32 repacked weights (scalar convs): [tap][cin][cout]
__device__ float g_w1a[27*3*64];
__device__ float g_w1b[27*64*64];
__device__ float g_w1d[3*64];
__device__ float g_wd1[27*64*128];
__device__ float g_wd3[27*256*128];
// bf16 hi/lo MMA weights: [tap][chunk64][COUT][64]
__device__ __nv_bfloat16 g_w2a_h[27*2*128*64], g_w2a_l[27*2*128*64];
__device__ __nv_bfloat16 g_w2b_h[27*2*128*64], g_w2b_l[27*2*128*64];
__device__ __nv_bfloat16 g_wd2_h[27*2*256*64], g_wd2_l[27*2*256*64];
__device__ __nv_bfloat16 g_w3a_h[27*4*256*64], g_w3a_l[27*4*256*64];
__device__ __nv_bfloat16 g_w3b_h[27*4*256*64], g_w3b_l[27*4*256*64];
// bf16 hi/lo activations (channel-last)
__device__ __nv_bfloat16 g_xd1h[NB*32768*128], g_xd1l[NB*32768*128];
__device__ __nv_bfloat16 g_t2h [NB*32768*128], g_t2l [NB*32768*128];
__device__ __nv_bfloat16 g_x2h [NB*32768*128], g_x2l [NB*32768*128];
__device__ __nv_bfloat16 g_xd2h[NB*4096*256],  g_xd2l[NB*4096*256];
__device__ __nv_bfloat16 g_t3h [NB*4096*256],  g_t3l [NB*4096*256];

__device__ __forceinline__ float lrelu(float v){ return v >= 0.f ? v : NEG*v; }
__device__ __forceinline__ unsigned sm_addr(const void* p){
    return (unsigned)__cvta_generic_to_shared(p);
}
__device__ __forceinline__ void split_bf16(float v, __nv_bfloat16& h, __nv_bfloat16& l){
    h = __float2bfloat16(v);
    l = __float2bfloat16(v - __bfloat162float(h));
}

// ---------------- mma.sync helpers ----------------
__device__ __forceinline__ void ldsm_x4(uint32_t a, uint32_t& r0, uint32_t& r1,
                                        uint32_t& r2, uint32_t& r3){
    asm volatile("ldmatrix.sync.aligned.m8n8.x4.shared.b16 {%0,%1,%2,%3}, [%4];"
                 : "=r"(r0), "=r"(r1), "=r"(r2), "=r"(r3) : "r"(a));
}
__device__ __forceinline__ void mma_bf16(float* c, const uint32_t* a,
                                         uint32_t b0, uint32_t b1){
    asm volatile(
        "mma.sync.aligned.m16n8k16.row.col.f32.bf16.bf16.f32 "
        "{%0,%1,%2,%3},{%4,%5,%6,%7},{%8,%9},{%0,%1,%2,%3};"
        : "+f"(c[0]), "+f"(c[1]), "+f"(c[2]), "+f"(c[3])
        : "r"(a[0]), "r"(a[1]), "r"(a[2]), "r"(a[3]), "r"(b0), "r"(b1));
}

// ---------------- setup kernels ----------------
struct RepackArgs {
    const float* src[5];
    float*       dst[5];
    int cin[5], cout[5], k3[5], start[5];
    int ntot;
};
__global__ void repack_all_k(RepackArgs a){
    int idx = blockIdx.x*blockDim.x + threadIdx.x;
    if (idx < 3) g_cnt[idx] = 0;
    if (idx >= a.ntot) return;
    int s = 0;
    #pragma unroll
    for (int k = 1; k < 5; k++) if (idx >= a.start[k]) s = k;
    int i = idx - a.start[s];
    int CIN = a.cin[s], COUT = a.cout[s], K3 = a.k3[s];
    int oc = i / (CIN*K3);
    int r  = i % (CIN*K3);
    int ic = r / K3;
    int k  = r % K3;
    a.dst[s][(k*CIN + ic)*COUT + oc] = a.src[s][i];
}

struct RepackMMA {
    const float* src[5];
    __nv_bfloat16 *dh[5], *dl[5];
    int cin[5], cout[5], start[5];
    int ntot;
};
__global__ void repack_mma_k(RepackMMA a){
    int idx = blockIdx.x*blockDim.x + threadIdx.x;
    if (idx >= a.ntot) return;
    int s = 0;
    #pragma unroll
    for (int k = 1; k < 5; k++) if (idx >= a.start[k]) s = k;
    int i = idx - a.start[s];
    int CIN = a.cin[s], COUT = a.cout[s];
    int oc = i / (CIN*27);
    int r  = i % (CIN*27);
    int ic = r / 27;
    int t  = r % 27;
    float v = a.src[s][i];
    __nv_bfloat16 h, l; split_bf16(v, h, l);
    int di = ((t*(CIN/64) + ic/64)*COUT + oc)*64 + (ic % 64);
    a.dh[s][di] = h;
    a.dl[s][di] = l;
}

__global__ void down_mask_k(const float* __restrict__ in, float* __restrict__ out,
                            int Din, int Dout){
    int i = blockIdx.x*blockDim.x + threadIdx.x;
    int tot = NB*Dout*Dout*Dout;
    if (i >= tot) return;
    int ox = i % Dout, t = i / Dout;
    int oy = t % Dout; t /= Dout;
    int oz = t % Dout; int b = t / Dout;
    float m = 0.f;
    for (int kz = 0; kz < 3; kz++){
        int iz = 2*oz - 1 + kz; if ((unsigned)iz >= (unsigned)Din) continue;
        for (int ky = 0; ky < 3; ky++){
            int iy = 2*oy - 1 + ky; if ((unsigned)iy >= (unsigned)Din) continue;
            for (int kx = 0; kx < 3; kx++){
                int ix = 2*ox - 1 + kx; if ((unsigned)ix >= (unsigned)Din) continue;
                m = fmaxf(m, in[((b*Din + iz)*Din + iy)*Din + ix]);
            }
        }
    }
    out[i] = m;
}

__global__ void fuse_k(const float* __restrict__ mask, const float* __restrict__ m2,
                       float* __restrict__ m3, int* __restrict__ l1,
                       int* __restrict__ l2, int* __restrict__ cnt){
    const int A = NB*262144, B = NB*32768, C = NB*4096;
    int idx = blockIdx.x*blockDim.x + threadIdx.x;
    if (idx < A){
        if (mask[idx] != 0.f){ int p = atomicAdd(cnt+0, 1); l1[p] = idx; }
    } else if (idx < A+B){
        int i = idx - A;
        if (m2[i] != 0.f){ int p = atomicAdd(cnt+1, 1); l2[p] = i; }
    } else if (idx < A+B+C){
        int i = idx - A - B;
        int ox = i % 16, t = i / 16;
        int oy = t % 16; t /= 16;
        int oz = t % 16; int b = t / 16;
        float m = 0.f;
        for (int kz = 0; kz < 3; kz++){
            int iz = 2*oz - 1 + kz; if ((unsigned)iz >= 32u) continue;
            for (int ky = 0; ky < 3; ky++){
                int iy = 2*oy - 1 + ky; if ((unsigned)iy >= 32u) continue;
                for (int kx = 0; kx < 3; kx++){
                    int ix = 2*ox - 1 + kx; if ((unsigned)ix >= 32u) continue;
                    m = fmaxf(m, m2[((b*32 + iz)*32 + iy)*32 + ix]);
                }
            }
        }
        m3[i] = m;
    }
}

__global__ void build_list_k(const float* __restrict__ m, int tot,
                             int* __restrict__ list, int* __restrict__ cnt){
    int i = blockIdx.x*blockDim.x + threadIdx.x;
    if (i < tot && m[i] != 0.f){
        int p = atomicAdd(cnt, 1);
        list[p] = i;
    }
}

// out fp32 (nullable) / outh+outl bf16 (nullable) = masked lrelu(in)
__global__ void fill_k(const float* __restrict__ in, const float* __restrict__ m,
                       float* __restrict__ out,
                       __nv_bfloat16* __restrict__ outh,
                       __nv_bfloat16* __restrict__ outl, int C, int n){
    int i  = blockIdx.x*blockDim.x + threadIdx.x;
    int st = gridDim.x*blockDim.x;
    for (int j = i; j < n; j += st){
        float v = in[j];
        float r = lrelu(v);
        if (m && m[j/C] == 0.f) r = 0.f;
        if (out) out[j] = r;
        if (outh){
            __nv_bfloat16 h, l; split_bf16(r, h, l);
            outh[j] = h; outl[j] = l;
        }
    }
}

// ---------------- simple conv (stage-1a: CIN=3, NCDHW in) ----------------
template<int CIN, int COUT, int CINC, int VB>
__global__ void __launch_bounds__(COUT) conv_s_k(
    const float* __restrict__ in, const float* __restrict__ wr,
    const float* __restrict__ in_mask,
    const int* __restrict__ list, const int* __restrict__ cnt,
    int Din, int Dout,
    float* __restrict__ out)
{
    __shared__ int s_base[VB];
    __shared__ int s_out [VB];
    __shared__ float s_in[VB][CINC];

    const int tid   = threadIdx.x;
    const int Din3  = Din*Din*Din;
    const int Dout3 = Dout*Dout*Dout;
    const int n     = *cnt;

    for (int vbase = blockIdx.x*VB; vbase < n; vbase += gridDim.x*VB){
        int vb=0,vz=0,vy=0,vx=0,vvalid=0;
        if (tid < VB){
            int vi = vbase + tid;
            int ob = -1;
            if (vi < n){
                int id = list[vi];
                vx = id % Dout; id /= Dout;
                vy = id % Dout; id /= Dout;
                vz = id % Dout; vb = id / Dout;
                ob = vb*Dout3 + (vz*Dout + vy)*Dout + vx;
                vvalid = 1;
            }
            s_out[tid] = ob;
        }
        __syncthreads();

        float acc[VB];
        #pragma unroll
        for (int v = 0; v < VB; v++) acc[v] = 0.f;

        for (int t = 0; t < 27; t++){
            int pred = 0;
            if (tid < VB){
                int base = -1;
                if (vvalid){
                    int kz = t/9, ky = (t/3)%3, kx = t%3;
                    int iz = vz - 1 + kz, iy = vy - 1 + ky, ix = vx - 1 + kx;
                    if ((unsigned)iz < (unsigned)Din && (unsigned)iy < (unsigned)Din &&
                        (unsigned)ix < (unsigned)Din){
                        int sp = (iz*Din + iy)*Din + ix;
                        if (in_mask[vb*Din3 + sp] != 0.f)
                            base = vb*CIN*Din3 + sp;
                    }
                }
                s_base[tid] = base;
                pred = (base >= 0);
            }
            if (!__syncthreads_or(pred)) continue;

            float wreg[CINC];
            #pragma unroll
            for (int c = 0; c < CINC; c++)
                wreg[c] = wr[(t*CIN + c)*COUT + tid];
            #pragma unroll 1
            for (int i = tid; i < CINC*VB; i += COUT){
                int v = i / CINC, c = i % CINC;
                int base = s_base[v];
                s_in[v][c] = (base >= 0) ? in[base + c*Din3] : 0.f;
            }
            __syncthreads();
            #pragma unroll
            for (int v = 0; v < VB; v++){
                float a = acc[v];
                #pragma unroll
                for (int c = 0; c < CINC; c++)
                    a = fmaf(wreg[c], s_in[v][c], a);
                acc[v] = a;
            }
            __syncthreads();
        }

        #pragma unroll
        for (int v = 0; v < VB; v++){
            int ob = s_out[v];
            if (ob < 0) continue;
            out[ob*COUT + tid] = lrelu(acc[v]);
        }
        __syncthreads();
    }
}

// ---------------- scalar pipelined conv (sparse stages) ----------------
template<int CIN, int COUT, int CINC, int VB>
__global__ void __launch_bounds__(COUT) convp_k(
    const float* __restrict__ in, const float* __restrict__ wr,
    const float* __restrict__ in_mask,
    const int* __restrict__ list, const int* __restrict__ cnt,
    int Din, int Dout, int stride,
    const float* __restrict__ ident,
    const float* __restrict__ identx, const float* __restrict__ identw,
    float* __restrict__ out,
    __nv_bfloat16* __restrict__ outh, __nv_bfloat16* __restrict__ outl)
{
    constexpr int CHUNKS = CIN/CINC;
    constexpr int F4 = VB*CINC/4;
    constexpr int PT = (F4 + COUT - 1)/COUT;
    __shared__ int s_tap[27];
    __shared__ int s_ntap;
    __shared__ int s_base[27][VB];
    __shared__ int s_out[VB];
    __shared__ __align__(16) float4 s_in[2][F4];

    const int tid   = threadIdx.x;
    const int Din3  = Din*Din*Din;
    const int Dout3 = Dout*Dout*Dout;
    const int n     = list ? *cnt : NB*Dout3;

    for (int vbase = blockIdx.x*VB; vbase < n; vbase += gridDim.x*VB){
        int vb=0,vz=0,vy=0,vx=0,vvalid=0;
        if (tid < VB){
            int vi = vbase + tid;
            int ob = -1;
            if (vi < n){
                int id = list ? list[vi] : vi;
                vx = id % Dout; id /= Dout;
                vy = id % Dout; id /= Dout;
                vz = id % Dout; vb = id / Dout;
                ob = vb*Dout3 + (vz*Dout + vy)*Dout + vx;
                vvalid = 1;
            }
            s_out[tid] = ob;
        }
        if (tid == 0) s_ntap = 0;
        __syncthreads();

        for (int t = 0; t < 27; t++){
            int pred = 0;
            if (tid < VB){
                int base = -1;
                if (vvalid){
                    int kz = t/9, ky = (t/3)%3, kx = t%3;
                    int iz = vz*stride - 1 + kz;
                    int iy = vy*stride - 1 + ky;
                    int ix = vx*stride - 1 + kx;
                    if ((unsigned)iz < (unsigned)Din && (unsigned)iy < (unsigned)Din &&
                        (unsigned)ix < (unsigned)Din){
                        int sp = (iz*Din + iy)*Din + ix;
                        if (!in_mask || in_mask[vb*Din3 + sp] != 0.f)
                            base = (vb*Din3 + sp)*CIN;
                    }
                }
                s_base[t][tid] = base;
                pred = (base >= 0);
            }
            int any = __syncthreads_or(pred);
            if (any && tid == 0) s_tap[s_ntap++] = t;
        }
        __syncthreads();
        const int ntap = s_ntap;
        const int nit  = ntap * CHUNKS;

        float acc[VB];
        #pragma unroll
        for (int v = 0; v < VB; v++) acc[v] = 0.f;

        auto issue = [&](int it, int buf){
            int tap = s_tap[it/CHUNKS];
            int cc  = (it%CHUNKS)*CINC;
            #pragma unroll
            for (int k = 0; k < PT; k++){
                int j = tid + k*COUT;
                if ((F4 % COUT == 0) || (j < F4)){
                    int v = j/(CINC/4), c4 = j%(CINC/4);
                    int base = s_base[tap][v];
                    const float* src = (base >= 0) ? (in + base + cc + c4*4) : in;
                    int sz = (base >= 0) ? 16 : 0;
                    unsigned dst = sm_addr(&s_in[buf][j]);
                    asm volatile("cp.async.ca.shared.global [%0], [%1], 16, %2;\n"
                                 :: "r"(dst), "l"(src), "r"(sz));
                }
            }
            asm volatile("cp.async.commit_group;\n");
        };

        if (nit > 0) issue(0, 0);
        for (int it = 0; it < nit; it++){
            int buf = it & 1;
            int tap = s_tap[it/CHUNKS];
            int cc  = (it%CHUNKS)*CINC;
            float wreg[CINC];
            #pragma unroll
            for (int c = 0; c < CINC; c++)
                wreg[c] = wr[(tap*CIN + cc + c)*COUT + tid];
            if (it + 1 < nit){
                issue(it + 1, buf ^ 1);
                asm volatile("cp.async.wait_group 1;\n");
            } else {
                asm volatile("cp.async.wait_group 0;\n");
            }
            __syncthreads();
            const float4* rows = s_in[buf];
            #pragma unroll
            for (int v = 0; v < VB; v++){
                float a = acc[v];
                #pragma unroll
                for (int q = 0; q < CINC/4; q++){
                    float4 r = rows[v*(CINC/4) + q];
                    a = fmaf(wreg[4*q+0], r.x, a);
                    a = fmaf(wreg[4*q+1], r.y, a);
                    a = fmaf(wreg[4*q+2], r.z, a);
                    a = fmaf(wreg[4*q+3], r.w, a);
                }
                acc[v] = a;
            }
            __syncthreads();
        }

        #pragma unroll
        for (int v = 0; v < VB; v++){
            int ob = s_out[v];
            if (ob < 0) continue;
            float val = acc[v];
            if (ident) val += ident[ob*COUT + tid];
            if (identx){
                int b = ob / Dout3, sp = ob - b*Dout3;
                const float* xp = identx + b*3*Dout3 + sp;
                val = fmaf(identw[tid],          xp[0],       val);
                val = fmaf(identw[COUT + tid],   xp[Dout3],   val);
                val = fmaf(identw[2*COUT + tid], xp[2*Dout3], val);
            }
            val = lrelu(val);
            if (out) out[ob*COUT + tid] = val;
            if (outh){
                __nv_bfloat16 h, l; split_bf16(val, h, l);
                outh[ob*COUT + tid] = h;
                outl[ob*COUT + tid] = l;
            }
        }
        __syncthreads();
    }
}

// ---------------- tensor conv via mma.sync (bf16 hi/lo split) ----------------
// 256 threads = 8 warps, 2D tiled: warp (wm,wn) owns 32 cout x 64 vox.
// Combo-major inner loop: all B frags preloaded, then hh/lh/hl passes of 16
// independent MMAs each (no back-to-back same-accumulator RAW chains).
template<int CIN, int COUT>
__global__ void __launch_bounds__(256) convt_k(
    const __nv_bfloat16* __restrict__ inh, const __nv_bfloat16* __restrict__ inl,
    const __nv_bfloat16* __restrict__ wh,  const __nv_bfloat16* __restrict__ wl,
    const float* __restrict__ in_mask,
    const int* __restrict__ list, const int* __restrict__ cnt,
    int Din, int Dout, int stride,
    const float* __restrict__ ident,
    float* __restrict__ out,
    __nv_bfloat16* __restrict__ outh, __nv_bfloat16* __restrict__ outl)
{
    constexpr int CHUNKS = CIN/64;
    constexpr int NV = 128;
    constexpr int PITCH = 144;
    constexpr int MATB = 128*PITCH;

    extern __shared__ char dsm[];
    __shared__ int s_tap[27];
    __shared__ int s_ntap;
    __shared__ int s_base[27][NV];
    __shared__ int s_out[NV];

    const int tid  = threadIdx.x;
    const int w    = tid >> 5, lane = tid & 31;
    const int wm   = w & 3, wn = w >> 2;
    const int ybase = blockIdx.y * 128;
    const int Din3  = Din*Din*Din;
    const int Dout3 = Dout*Dout*Dout;
    const int n     = list ? *cnt : NB*Dout3;

    const int g  = lane >> 2;
    const int t4 = lane & 3;

    for (int vbase = blockIdx.x*NV; vbase < n; vbase += gridDim.x*NV){
        if (tid < NV){
            int vi = vbase + tid;
            int ob = -1;
            if (vi < n){
                int id = list ? list[vi] : vi;
                int vx = id % Dout; id /= Dout;
                int vy = id % Dout; id /= Dout;
                int vz = id % Dout; int vb = id / Dout;
                ob = vb*Dout3 + (vz*Dout + vy)*Dout + vx;
            }
            s_out[tid] = ob;
        }
        if (tid == 0) s_ntap = 0;
        __syncthreads();

        for (int t = 0; t < 27; t++){
            int base = -1;
            if (tid < NV && s_out[tid] >= 0){
                int id = list ? list[vbase + tid] : (vbase + tid);
                int vx = id % Dout; id /= Dout;
                int vy = id % Dout; id /= Dout;
                int vz = id % Dout; int vb = id / Dout;
                int kz = t/9, ky = (t/3)%3, kx = t%3;
                int iz = vz*stride - 1 + kz;
                int iy = vy*stride - 1 + ky;
                int ix = vx*stride - 1 + kx;
                if ((unsigned)iz < (unsigned)Din && (unsigned)iy < (unsigned)Din &&
                    (unsigned)ix < (unsigned)Din){
                    int sp = (iz*Din + iy)*Din + ix;
                    if (!in_mask || in_mask[vb*Din3 + sp] != 0.f)
                        base = (vb*Din3 + sp)*CIN;
                }
            }
            if (tid < NV) s_base[t][tid] = base;
            int any = __syncthreads_or(base >= 0);
            if (any && tid == 0) s_tap[s_ntap++] = t;
        }
        __syncthreads();
        const int ntap = s_ntap;
        const int nit  = ntap * CHUNKS;

        float acc[2][8][4];
        #pragma unroll
        for (int mi = 0; mi < 2; mi++)
            #pragma unroll
            for (int nt = 0; nt < 8; nt++)
                #pragma unroll
                for (int e = 0; e < 4; e++) acc[mi][nt][e] = 0.f;

        auto issue = [&](int it, int buf){
            int tap = s_tap[it/CHUNKS];
            int ch  = it%CHUNKS;
            char* Ah = dsm + buf*4*MATB;
            char* Al = Ah + MATB;
            char* Bh = Ah + 2*MATB;
            char* Bl = Ah + 3*MATB;
            const __nv_bfloat16* wsrcH = wh + (size_t)((tap*CHUNKS + ch)*COUT + ybase)*64;
            const __nv_bfloat16* wsrcL = wl + (size_t)((tap*CHUNKS + ch)*COUT + ybase)*64;
            #pragma unroll
            for (int j = 0; j < 4; j++){
                int idx = tid*4 + j;
                int row = idx >> 3, col = idx & 7;
                unsigned off = row*PITCH + col*16;
                asm volatile("cp.async.ca.shared.global [%0], [%1], 16;\n"
                    :: "r"(sm_addr(Ah) + off), "l"(wsrcH + row*64 + col*8));
                asm volatile("cp.async.ca.shared.global [%0], [%1], 16;\n"
                    :: "r"(sm_addr(Al) + off), "l"(wsrcL + row*64 + col*8));
                int base = s_base[tap][row];
                const __nv_bfloat16* bsrcH = (base >= 0) ? (inh + base + ch*64 + col*8) : inh;
                const __nv_bfloat16* bsrcL = (base >= 0) ? (inl + base + ch*64 + col*8) : inl;
                int sz = (base >= 0) ? 16 : 0;
                asm volatile("cp.async.ca.shared.global [%0], [%1], 16, %2;\n"
                    :: "r"(sm_addr(Bh) + off), "l"(bsrcH), "r"(sz));
                asm volatile("cp.async.ca.shared.global [%0], [%1], 16, %2;\n"
                    :: "r"(sm_addr(Bl) + off), "l"(bsrcL), "r"(sz));
            }
            asm volatile("cp.async.commit_group;\n");
        };

        if (nit > 0) issue(0, 0);
        for (int it = 0; it < nit; it++){
            int buf = it & 1;
            if (it + 1 < nit){
                issue(it + 1, buf ^ 1);
                asm volatile("cp.async.wait_group 1;\n");
            } else {
                asm volatile("cp.async.wait_group 0;\n");
            }
            __syncthreads();
            unsigned Ah = sm_addr(dsm) + buf*4*MATB;
            unsigned Al = Ah + MATB;
            unsigned Bh = Ah + 2*MATB;
            unsigned Bl = Ah + 3*MATB;
            unsigned arow0 = (unsigned)(wm*32 + (lane & 15))*PITCH + ((lane >> 4)*16);
            // B x4 addressing: lanes 0-7 -> nt=2p rows (+0), 8-15 -> nt=2p (+16),
            // 16-23 -> nt=2p+1 (+0), 24-31 -> nt=2p+1 (+16)
            unsigned brow0 = (unsigned)(wn*64 + ((lane >> 4) & 1)*8 + (lane & 7))*PITCH
                           + (((lane >> 3) & 1)*16);
            #pragma unroll
            for (int ks = 0; ks < 4; ks++){
                uint32_t ah[2][4], al[2][4];
                #pragma unroll
                for (int mi = 0; mi < 2; mi++){
                    ldsm_x4(Ah + arow0 + mi*16*PITCH + ks*32,
                            ah[mi][0], ah[mi][1], ah[mi][2], ah[mi][3]);
                    ldsm_x4(Al + arow0 + mi*16*PITCH + ks*32,
                            al[mi][0], al[mi][1], al[mi][2], al[mi][3]);
                }
                uint32_t bh[16], bl[16];   // [nt*2 + (b0/b1)]
                #pragma unroll
                for (int p = 0; p < 4; p++){
                    unsigned boff = brow0 + (unsigned)p*16*PITCH + ks*32;
                    ldsm_x4(Bh + boff, bh[4*p+0], bh[4*p+1], bh[4*p+2], bh[4*p+3]);
                    ldsm_x4(Bl + boff, bl[4*p+0], bl[4*p+1], bl[4*p+2], bl[4*p+3]);
                }
                // combo-major passes: every consecutive MMA hits a different acc
                #pragma unroll
                for (int nt = 0; nt < 8; nt++)
                    #pragma unroll
                    for (int mi = 0; mi < 2; mi++)
                        mma_bf16(acc[mi][nt], ah[mi], bh[2*nt], bh[2*nt+1]);
                #pragma unroll
                for (int nt = 0; nt < 8; nt++)
                    #pragma unroll
                    for (int mi = 0; mi < 2; mi++)
                        mma_bf16(acc[mi][nt], al[mi], bh[2*nt], bh[2*nt+1]);
                #pragma unroll
                for (int nt = 0; nt < 8; nt++)
                    #pragma unroll
                    for (int mi = 0; mi < 2; mi++)
                        mma_bf16(acc[mi][nt], ah[mi], bl[2*nt], bl[2*nt+1]);
            }
            __syncthreads();
        }

        // epilogue: lane holds D[cout=wm*32+mi*16+g(+8)][vox=wn*64+nt*8+t4*2(+1)]
        #pragma unroll
        for (int mi = 0; mi < 2; mi++){
            #pragma unroll
            for (int nt = 0; nt < 8; nt++){
                #pragma unroll
                for (int e = 0; e < 4; e++){
                    int v  = wn*64 + nt*8 + t4*2 + (e & 1);
                    int co = ybase + wm*32 + mi*16 + g + ((e >> 1)*8);
                    int ob = s_out[v];
                    if (ob < 0) continue;
                    float val = acc[mi][nt][e];
                    if (ident) val += ident[(size_t)ob*COUT + co];
                    val = lrelu(val);
                    size_t oi = (size_t)ob*COUT + co;
                    if (out) out[oi] = val;
                    if (outh){
                        __nv_bfloat16 h, l; split_bf16(val, h, l);
                        outh[oi] = h; outl[oi] = l;
                    }
                }
            }
        }
        __syncthreads();
    }
}

// ---------------- final pooled reduce ----------------
__global__ void reduce_k(const float* __restrict__ x4, float* __restrict__ out){
    int b  = blockIdx.x;
    int oc = threadIdx.x;
    const float* p = x4 + b*512*128 + oc;
    float s = 0.f, mx = -3.402823466e38f;
    #pragma unroll 8
    for (int sp = 0; sp < 512; sp++){
        float v = p[sp*128];
        s += v; mx = fmaxf(mx, v);
    }
    out[b*256 + oc]       = s * (1.f/512.f);
    out[b*256 + 128 + oc] = mx;
}

// ---------------- launch ----------------
extern "C" void kernel_launch(void* const* d_in, const int* in_sizes, int n_in,
                              void* d_out, int out_size){
    const float* x    = (const float*)d_in[0];
    const float* mask = (const float*)d_in[1];
    float* out = (float*)d_out;

    float *t1,*x1,*xd1,*x3,*xd2,*x4,*m2,*m3;
    int *l1,*l2,*l3,*cnt;
    cudaGetSymbolAddress((void**)&t1 , g_t1 );
    cudaGetSymbolAddress((void**)&x1 , g_x1 );
    cudaGetSymbolAddress((void**)&xd1, g_xd1);
    cudaGetSymbolAddress((void**)&x3 , g_x3 );
    cudaGetSymbolAddress((void**)&xd2, g_xd2);
    cudaGetSymbolAddress((void**)&x4 , g_x4 );
    cudaGetSymbolAddress((void**)&m2 , g_m2 );
    cudaGetSymbolAddress((void**)&m3 , g_m3 );
    cudaGetSymbolAddress((void**)&l1 , g_list1);
    cudaGetSymbolAddress((void**)&l2 , g_list2);
    cudaGetSymbolAddress((void**)&l3 , g_list3);
    cudaGetSymbolAddress((void**)&cnt, g_cnt);

    float *w1ar,*w1br,*w1dr,*wd1r,*wd3r;
    cudaGetSymbolAddress((void**)&w1ar, g_w1a);
    cudaGetSymbolAddress((void**)&w1br, g_w1b);
    cudaGetSymbolAddress((void**)&w1dr, g_w1d);
    cudaGetSymbolAddress((void**)&wd1r, g_wd1);
    cudaGetSymbolAddress((void**)&wd3r, g_wd3);

    __nv_bfloat16 *w2ah,*w2al,*w2bh,*w2bl,*wd2h,*wd2l,*w3ah,*w3al,*w3bh,*w3bl;
    cudaGetSymbolAddress((void**)&w2ah, g_w2a_h); cudaGetSymbolAddress((void**)&w2al, g_w2a_l);
    cudaGetSymbolAddress((void**)&w2bh, g_w2b_h); cudaGetSymbolAddress((void**)&w2bl, g_w2b_l);
    cudaGetSymbolAddress((void**)&wd2h, g_wd2_h); cudaGetSymbolAddress((void**)&wd2l, g_wd2_l);
    cudaGetSymbolAddress((void**)&w3ah, g_w3a_h); cudaGetSymbolAddress((void**)&w3al, g_w3a_l);
    cudaGetSymbolAddress((void**)&w3bh, g_w3b_h); cudaGetSymbolAddress((void**)&w3bl, g_w3b_l);

    __nv_bfloat16 *xd1h,*xd1l,*t2h,*t2l,*x2h,*x2l,*xd2h,*xd2l,*t3h,*t3l;
    cudaGetSymbolAddress((void**)&xd1h, g_xd1h); cudaGetSymbolAddress((void**)&xd1l, g_xd1l);
    cudaGetSymbolAddress((void**)&t2h,  g_t2h ); cudaGetSymbolAddress((void**)&t2l,  g_t2l );
    cudaGetSymbolAddress((void**)&x2h,  g_x2h ); cudaGetSymbolAddress((void**)&x2l,  g_x2l );
    cudaGetSymbolAddress((void**)&xd2h, g_xd2h); cudaGetSymbolAddress((void**)&xd2l, g_xd2l);
    cudaGetSymbolAddress((void**)&t3h,  g_t3h ); cudaGetSymbolAddress((void**)&t3l,  g_t3l );

    RepackArgs ra;
    {
        const float* src[5] = {(const float*)d_in[2], (const float*)d_in[4],
                               (const float*)d_in[3], (const float*)d_in[5],
                               (const float*)d_in[11]};
        float* dst[5] = {w1ar, w1dr, w1br, wd1r, wd3r};
        const int cins[5]  = {3, 3, 64, 64, 256};
        const int couts[5] = {64,64, 64,128, 128};
        const int k3s[5]   = {27, 1, 27, 27, 27};
        int off = 0;
        for (int i = 0; i < 5; i++){
            ra.src[i]=src[i]; ra.dst[i]=dst[i];
            ra.cin[i]=cins[i]; ra.cout[i]=couts[i]; ra.k3[i]=k3s[i];
            ra.start[i]=off; off += cins[i]*couts[i]*k3s[i];
        }
        ra.ntot = off;
    }
    RepackMMA rm;
    {
        const float* src[5] = {(const float*)d_in[6], (const float*)d_in[7],
                               (const float*)d_in[8], (const float*)d_in[9],
                               (const float*)d_in[10]};
        __nv_bfloat16* dh[5] = {w2ah, w2bh, wd2h, w3ah, w3bh};
        __nv_bfloat16* dl[5] = {w2al, w2bl, wd2l, w3al, w3bl};
        const int cins[5]  = {128, 128, 128, 256, 256};
        const int couts[5] = {128, 128, 256, 256, 256};
        int off = 0;
        for (int i = 0; i < 5; i++){
            rm.src[i]=src[i]; rm.dh[i]=dh[i]; rm.dl[i]=dl[i];
            rm.cin[i]=cins[i]; rm.cout[i]=couts[i];
            rm.start[i]=off; off += cins[i]*couts[i]*27;
        }
        rm.ntot = off;
    }

    const int DSM = 2*4*128*144;   // 147456 B
    cudaFuncSetAttribute(convt_k<128,128>, cudaFuncAttributeMaxDynamicSharedMemorySize, DSM);
    cudaFuncSetAttribute(convt_k<128,256>, cudaFuncAttributeMaxDynamicSharedMemorySize, DSM);
    cudaFuncSetAttribute(convt_k<256,256>, cudaFuncAttributeMaxDynamicSharedMemorySize, DSM);

    repack_all_k<<<(ra.ntot + 255)/256, 256>>>(ra);
    repack_mma_k<<<(rm.ntot + 255)/256, 256>>>(rm);
    down_mask_k<<<(NB*32768 + 255)/256, 256>>>(mask, m2, 64, 32);
    fuse_k<<<(NB*262144 + NB*32768 + NB*4096 + 255)/256, 256>>>(mask, m2, m3, l1, l2, cnt);
    build_list_k<<<(NB*4096 + 255)/256, 256>>>(m3, NB*4096, l3, cnt+2);

    // ---- stage 1 + down1 (scalar, sparse); down1 emits bf16 hi/lo fused ----
    conv_s_k<3,64,3,8><<<2048,64>>>(x, w1ar, mask, l1, cnt+0, 64, 64, t1);
    convp_k<64,64,16,8><<<4096,64>>>(t1, w1br, mask, l1, cnt+0, 64,64,1,
                                     nullptr, x, w1dr, x1, nullptr, nullptr);
    convp_k<64,128,16,8><<<2048,128>>>(x1, wd1r, mask, l2, cnt+1, 64,32,2,
                                       nullptr, nullptr, nullptr, xd1, xd1h, xd1l);
    // ---- stage 2 (tensor; bf16 outputs fused, fp32 skipped where unused) ----
    convt_k<128,128><<<dim3(512,1),256,DSM>>>(xd1h, xd1l, w2ah, w2al, m2,
                                              l2, cnt+1, 32,32,1, nullptr,
                                              nullptr, t2h, t2l);
    fill_k<<<2048,256>>>(xd1, m2, nullptr, x2h, x2l, 128, NB*32768*128);
    convt_k<128,128><<<dim3(512,1),256,DSM>>>(t2h, t2l, w2bh, w2bl, m2,
                                              l2, cnt+1, 32,32,1, xd1,
                                              nullptr, x2h, x2l);
    // ---- down2 (tensor, dense, stride 2; fp32 needed as stage-3b ident) ----
    convt_k<128,256><<<dim3(64,2),256,DSM>>>(x2h, x2l, wd2h, wd2l, nullptr,
                                             nullptr, nullptr, 32,16,2, nullptr,
                                             xd2, xd2h, xd2l);
    // ---- stage 3 (tensor) ----
    convt_k<256,256><<<dim3(64,2),256,DSM>>>(xd2h, xd2l, w3ah, w3al, nullptr,
                                             l3, cnt+2, 16,16,1, nullptr,
                                             nullptr, t3h, t3l);
    fill_k<<<1024,256>>>(xd2, nullptr, x3, nullptr, nullptr, 256, NB*4096*256);
    convt_k<256,256><<<dim3(64,2),256,DSM>>>(t3h, t3l, w3bh, w3bl, m3,
                                             l3, cnt+2, 16,16,1, xd2,
                                             x3, nullptr, nullptr);
    // ---- down3 (scalar) ----
    convp_k<256,128,16,8><<<128,128>>>(x3, wd3r, nullptr, nullptr, nullptr,
                                       16,8,2, nullptr, nullptr, nullptr,
                                       x4, nullptr, nullptr);
    reduce_k<<<2,128>>>(x4, out);
}

// round 16
// speedup vs baseline: 2.1981x; 1.0166x over previous
#include <cuda_runtime.h>
#include <cuda_bf16.h>
#include <cstdint>

#define NB 2
#define NEG 0.2f

// ---------------- scratch (__device__ globals; no allocation) ----------------
__device__ float g_t1 [NB*64*64*64*64];
__device__ float g_xd1[NB*32*32*32*128];
__device__ float g_xd2[NB*16*16*16*256];
__device__ float g_x4 [NB*8*8*8*128];
__device__ float g_m2 [NB*32*32*32];
__device__ float g_m3 [NB*16*16*16];
__device__ int   g_list1[NB*64*64*64];
__device__ int   g_list2[NB*32*32*32];
__device__ int   g_list3[NB*16*16*16];
__device__ int   g_cnt[3];
// fp32 repacked weights (scalar convs): [tap][cin][cout]
__device__ float g_w1a[27*3*64];
__device__ float g_w1b[27*64*64];
__device__ float g_w1d[3*64];
// bf16 hi/lo MMA weights: [tap][chunk64][COUT][64]
__device__ __nv_bfloat16 g_wd1_h[27*1*128*64], g_wd1_l[27*1*128*64];
__device__ __nv_bfloat16 g_w2a_h[27*2*128*64], g_w2a_l[27*2*128*64];
__device__ __nv_bfloat16 g_w2b_h[27*2*128*64], g_w2b_l[27*2*128*64];
__device__ __nv_bfloat16 g_wd2_h[27*2*256*64], g_wd2_l[27*2*256*64];
__device__ __nv_bfloat16 g_w3a_h[27*4*256*64], g_w3a_l[27*4*256*64];
__device__ __nv_bfloat16 g_w3b_h[27*4*256*64], g_w3b_l[27*4*256*64];
__device__ __nv_bfloat16 g_wd3_h[27*4*128*64], g_wd3_l[27*4*128*64];
// bf16 hi/lo activations (channel-last)
__device__ __nv_bfloat16 g_x1h [NB*262144*64], g_x1l [NB*262144*64];
__device__ __nv_bfloat16 g_xd1h[NB*32768*128], g_xd1l[NB*32768*128];
__device__ __nv_bfloat16 g_t2h [NB*32768*128], g_t2l [NB*32768*128];
__device__ __nv_bfloat16 g_x2h [NB*32768*128], g_x2l [NB*32768*128];
__device__ __nv_bfloat16 g_xd2h[NB*4096*256],  g_xd2l[NB*4096*256];
__device__ __nv_bfloat16 g_t3h [NB*4096*256],  g_t3l [NB*4096*256];
__device__ __nv_bfloat16 g_x3h [NB*4096*256],  g_x3l [NB*4096*256];

__device__ __forceinline__ float lrelu(float v){ return v >= 0.f ? v : NEG*v; }
__device__ __forceinline__ unsigned sm_addr(const void* p){
    return (unsigned)__cvta_generic_to_shared(p);
}
__device__ __forceinline__ void split_bf16(float v, __nv_bfloat16& h, __nv_bfloat16& l){
    h = __float2bfloat16(v);
    l = __float2bfloat16(v - __bfloat162float(h));
}

// ---------------- mma.sync helpers ----------------
__device__ __forceinline__ void ldsm_x4(uint32_t a, uint32_t& r0, uint32_t& r1,
                                        uint32_t& r2, uint32_t& r3){
    asm volatile("ldmatrix.sync.aligned.m8n8.x4.shared.b16 {%0,%1,%2,%3}, [%4];"
                 : "=r"(r0), "=r"(r1), "=r"(r2), "=r"(r3) : "r"(a));
}
__device__ __forceinline__ void mma_bf16(float* c, const uint32_t* a,
                                         uint32_t b0, uint32_t b1){
    asm volatile(
        "mma.sync.aligned.m16n8k16.row.col.f32.bf16.bf16.f32 "
        "{%0,%1,%2,%3},{%4,%5,%6,%7},{%8,%9},{%0,%1,%2,%3};"
        : "+f"(c[0]), "+f"(c[1]), "+f"(c[2]), "+f"(c[3])
        : "r"(a[0]), "r"(a[1]), "r"(a[2]), "r"(a[3]), "r"(b0), "r"(b1));
}

// ---------------- setup kernels ----------------
struct RepackArgs {
    const float* src[3];
    float*       dst[3];
    int cin[3], cout[3], k3[3], start[3];
    int ntot;
};
__global__ void repack_all_k(RepackArgs a){
    int idx = blockIdx.x*blockDim.x + threadIdx.x;
    if (idx < 3) g_cnt[idx] = 0;
    if (idx >= a.ntot) return;
    int s = 0;
    #pragma unroll
    for (int k = 1; k < 3; k++) if (idx >= a.start[k]) s = k;
    int i = idx - a.start[s];
    int CIN = a.cin[s], COUT = a.cout[s], K3 = a.k3[s];
    int oc = i / (CIN*K3);
    int r  = i % (CIN*K3);
    int ic = r / K3;
    int k  = r % K3;
    a.dst[s][(k*CIN + ic)*COUT + oc] = a.src[s][i];
}

struct RepackMMA {
    const float* src[7];
    __nv_bfloat16 *dh[7], *dl[7];
    int cin[7], cout[7], start[7];
    int ntot;
};
__global__ void repack_mma_k(RepackMMA a){
    int idx = blockIdx.x*blockDim.x + threadIdx.x;
    if (idx >= a.ntot) return;
    int s = 0;
    #pragma unroll
    for (int k = 1; k < 7; k++) if (idx >= a.start[k]) s = k;
    int i = idx - a.start[s];
    int CIN = a.cin[s], COUT = a.cout[s];
    int oc = i / (CIN*27);
    int r  = i % (CIN*27);
    int ic = r / 27;
    int t  = r % 27;
    float v = a.src[s][i];
    __nv_bfloat16 h, l; split_bf16(v, h, l);
    int di = ((t*(CIN/64) + ic/64)*COUT + oc)*64 + (ic % 64);
    a.dh[s][di] = h;
    a.dl[s][di] = l;
}

__global__ void down_mask_k(const float* __restrict__ in, float* __restrict__ out,
                            int Din, int Dout){
    int i = blockIdx.x*blockDim.x + threadIdx.x;
    int tot = NB*Dout*Dout*Dout;
    if (i >= tot) return;
    int ox = i % Dout, t = i / Dout;
    int oy = t % Dout; t /= Dout;
    int oz = t % Dout; int b = t / Dout;
    float m = 0.f;
    for (int kz = 0; kz < 3; kz++){
        int iz = 2*oz - 1 + kz; if ((unsigned)iz >= (unsigned)Din) continue;
        for (int ky = 0; ky < 3; ky++){
            int iy = 2*oy - 1 + ky; if ((unsigned)iy >= (unsigned)Din) continue;
            for (int kx = 0; kx < 3; kx++){
                int ix = 2*ox - 1 + kx; if ((unsigned)ix >= (unsigned)Din) continue;
                m = fmaxf(m, in[((b*Din + iz)*Din + iy)*Din + ix]);
            }
        }
    }
    out[i] = m;
}

__global__ void fuse_k(const float* __restrict__ mask, const float* __restrict__ m2,
                       float* __restrict__ m3, int* __restrict__ l1,
                       int* __restrict__ l2, int* __restrict__ cnt){
    const int A = NB*262144, B = NB*32768, C = NB*4096;
    int idx = blockIdx.x*blockDim.x + threadIdx.x;
    if (idx < A){
        if (mask[idx] != 0.f){ int p = atomicAdd(cnt+0, 1); l1[p] = idx; }
    } else if (idx < A+B){
        int i = idx - A;
        if (m2[i] != 0.f){ int p = atomicAdd(cnt+1, 1); l2[p] = i; }
    } else if (idx < A+B+C){
        int i = idx - A - B;
        int ox = i % 16, t = i / 16;
        int oy = t % 16; t /= 16;
        int oz = t % 16; int b = t / 16;
        float m = 0.f;
        for (int kz = 0; kz < 3; kz++){
            int iz = 2*oz - 1 + kz; if ((unsigned)iz >= 32u) continue;
            for (int ky = 0; ky < 3; ky++){
                int iy = 2*oy - 1 + ky; if ((unsigned)iy >= 32u) continue;
                for (int kx = 0; kx < 3; kx++){
                    int ix = 2*ox - 1 + kx; if ((unsigned)ix >= 32u) continue;
                    m = fmaxf(m, m2[((b*32 + iz)*32 + iy)*32 + ix]);
                }
            }
        }
        m3[i] = m;
    }
}

__global__ void build_list_k(const float* __restrict__ m, int tot,
                             int* __restrict__ list, int* __restrict__ cnt){
    int i = blockIdx.x*blockDim.x + threadIdx.x;
    if (i < tot && m[i] != 0.f){
        int p = atomicAdd(cnt, 1);
        list[p] = i;
    }
}

// out fp32 (nullable) / outh+outl bf16 (nullable) = masked lrelu(in)
__global__ void fill_k(const float* __restrict__ in, const float* __restrict__ m,
                       float* __restrict__ out,
                       __nv_bfloat16* __restrict__ outh,
                       __nv_bfloat16* __restrict__ outl, int C, int n){
    int i  = blockIdx.x*blockDim.x + threadIdx.x;
    int st = gridDim.x*blockDim.x;
    for (int j = i; j < n; j += st){
        float v = in[j];
        float r = lrelu(v);
        if (m && m[j/C] == 0.f) r = 0.f;
        if (out) out[j] = r;
        if (outh){
            __nv_bfloat16 h, l; split_bf16(r, h, l);
            outh[j] = h; outl[j] = l;
        }
    }
}

// ---------------- simple conv (stage-1a: CIN=3, NCDHW in) ----------------
template<int CIN, int COUT, int CINC, int VB>
__global__ void __launch_bounds__(COUT) conv_s_k(
    const float* __restrict__ in, const float* __restrict__ wr,
    const float* __restrict__ in_mask,
    const int* __restrict__ list, const int* __restrict__ cnt,
    int Din, int Dout,
    float* __restrict__ out)
{
    __shared__ int s_base[VB];
    __shared__ int s_out [VB];
    __shared__ float s_in[VB][CINC];

    const int tid   = threadIdx.x;
    const int Din3  = Din*Din*Din;
    const int Dout3 = Dout*Dout*Dout;
    const int n     = *cnt;

    for (int vbase = blockIdx.x*VB; vbase < n; vbase += gridDim.x*VB){
        int vb=0,vz=0,vy=0,vx=0,vvalid=0;
        if (tid < VB){
            int vi = vbase + tid;
            int ob = -1;
            if (vi < n){
                int id = list[vi];
                vx = id % Dout; id /= Dout;
                vy = id % Dout; id /= Dout;
                vz = id % Dout; vb = id / Dout;
                ob = vb*Dout3 + (vz*Dout + vy)*Dout + vx;
                vvalid = 1;
            }
            s_out[tid] = ob;
        }
        __syncthreads();

        float acc[VB];
        #pragma unroll
        for (int v = 0; v < VB; v++) acc[v] = 0.f;

        for (int t = 0; t < 27; t++){
            int pred = 0;
            if (tid < VB){
                int base = -1;
                if (vvalid){
                    int kz = t/9, ky = (t/3)%3, kx = t%3;
                    int iz = vz - 1 + kz, iy = vy - 1 + ky, ix = vx - 1 + kx;
                    if ((unsigned)iz < (unsigned)Din && (unsigned)iy < (unsigned)Din &&
                        (unsigned)ix < (unsigned)Din){
                        int sp = (iz*Din + iy)*Din + ix;
                        if (in_mask[vb*Din3 + sp] != 0.f)
                            base = vb*CIN*Din3 + sp;
                    }
                }
                s_base[tid] = base;
                pred = (base >= 0);
            }
            if (!__syncthreads_or(pred)) continue;

            float wreg[CINC];
            #pragma unroll
            for (int c = 0; c < CINC; c++)
                wreg[c] = wr[(t*CIN + c)*COUT + tid];
            #pragma unroll 1
            for (int i = tid; i < CINC*VB; i += COUT){
                int v = i / CINC, c = i % CINC;
                int base = s_base[v];
                s_in[v][c] = (base >= 0) ? in[base + c*Din3] : 0.f;
            }
            __syncthreads();
            #pragma unroll
            for (int v = 0; v < VB; v++){
                float a = acc[v];
                #pragma unroll
                for (int c = 0; c < CINC; c++)
                    a = fmaf(wreg[c], s_in[v][c], a);
                acc[v] = a;
            }
            __syncthreads();
        }

        #pragma unroll
        for (int v = 0; v < VB; v++){
            int ob = s_out[v];
            if (ob < 0) continue;
            out[ob*COUT + tid] = lrelu(acc[v]);
        }
        __syncthreads();
    }
}

// ---------------- scalar pipelined conv (stage-1b only) ----------------
template<int CIN, int COUT, int CINC, int VB>
__global__ void __launch_bounds__(COUT) convp_k(
    const float* __restrict__ in, const float* __restrict__ wr,
    const float* __restrict__ in_mask,
    const int* __restrict__ list, const int* __restrict__ cnt,
    int Din, int Dout, int stride,
    const float* __restrict__ ident,
    const float* __restrict__ identx, const float* __restrict__ identw,
    float* __restrict__ out,
    __nv_bfloat16* __restrict__ outh, __nv_bfloat16* __restrict__ outl)
{
    constexpr int CHUNKS = CIN/CINC;
    constexpr int F4 = VB*CINC/4;
    constexpr int PT = (F4 + COUT - 1)/COUT;
    __shared__ int s_tap[27];
    __shared__ int s_ntap;
    __shared__ int s_base[27][VB];
    __shared__ int s_out[VB];
    __shared__ __align__(16) float4 s_in[2][F4];

    const int tid   = threadIdx.x;
    const int Din3  = Din*Din*Din;
    const int Dout3 = Dout*Dout*Dout;
    const int n     = list ? *cnt : NB*Dout3;

    for (int vbase = blockIdx.x*VB; vbase < n; vbase += gridDim.x*VB){
        int vb=0,vz=0,vy=0,vx=0,vvalid=0;
        if (tid < VB){
            int vi = vbase + tid;
            int ob = -1;
            if (vi < n){
                int id = list ? list[vi] : vi;
                vx = id % Dout; id /= Dout;
                vy = id % Dout; id /= Dout;
                vz = id % Dout; vb = id / Dout;
                ob = vb*Dout3 + (vz*Dout + vy)*Dout + vx;
                vvalid = 1;
            }
            s_out[tid] = ob;
        }
        if (tid == 0) s_ntap = 0;
        __syncthreads();

        for (int t = 0; t < 27; t++){
            int pred = 0;
            if (tid < VB){
                int base = -1;
                if (vvalid){
                    int kz = t/9, ky = (t/3)%3, kx = t%3;
                    int iz = vz*stride - 1 + kz;
                    int iy = vy*stride - 1 + ky;
                    int ix = vx*stride - 1 + kx;
                    if ((unsigned)iz < (unsigned)Din && (unsigned)iy < (unsigned)Din &&
                        (unsigned)ix < (unsigned)Din){
                        int sp = (iz*Din + iy)*Din + ix;
                        if (!in_mask || in_mask[vb*Din3 + sp] != 0.f)
                            base = (vb*Din3 + sp)*CIN;
                    }
                }
                s_base[t][tid] = base;
                pred = (base >= 0);
            }
            int any = __syncthreads_or(pred);
            if (any && tid == 0) s_tap[s_ntap++] = t;
        }
        __syncthreads();
        const int ntap = s_ntap;
        const int nit  = ntap * CHUNKS;

        float acc[VB];
        #pragma unroll
        for (int v = 0; v < VB; v++) acc[v] = 0.f;

        auto issue = [&](int it, int buf){
            int tap = s_tap[it/CHUNKS];
            int cc  = (it%CHUNKS)*CINC;
            #pragma unroll
            for (int k = 0; k < PT; k++){
                int j = tid + k*COUT;
                if ((F4 % COUT == 0) || (j < F4)){
                    int v = j/(CINC/4), c4 = j%(CINC/4);
                    int base = s_base[tap][v];
                    const float* src = (base >= 0) ? (in + base + cc + c4*4) : in;
                    int sz = (base >= 0) ? 16 : 0;
                    unsigned dst = sm_addr(&s_in[buf][j]);
                    asm volatile("cp.async.ca.shared.global [%0], [%1], 16, %2;\n"
                                 :: "r"(dst), "l"(src), "r"(sz));
                }
            }
            asm volatile("cp.async.commit_group;\n");
        };

        if (nit > 0) issue(0, 0);
        for (int it = 0; it < nit; it++){
            int buf = it & 1;
            int tap = s_tap[it/CHUNKS];
            int cc  = (it%CHUNKS)*CINC;
            float wreg[CINC];
            #pragma unroll
            for (int c = 0; c < CINC; c++)
                wreg[c] = wr[(tap*CIN + cc + c)*COUT + tid];
            if (it + 1 < nit){
                issue(it + 1, buf ^ 1);
                asm volatile("cp.async.wait_group 1;\n");
            } else {
                asm volatile("cp.async.wait_group 0;\n");
            }
            __syncthreads();
            const float4* rows = s_in[buf];
            #pragma unroll
            for (int v = 0; v < VB; v++){
                float a = acc[v];
                #pragma unroll
                for (int q = 0; q < CINC/4; q++){
                    float4 r = rows[v*(CINC/4) + q];
                    a = fmaf(wreg[4*q+0], r.x, a);
                    a = fmaf(wreg[4*q+1], r.y, a);
                    a = fmaf(wreg[4*q+2], r.z, a);
                    a = fmaf(wreg[4*q+3], r.w, a);
                }
                acc[v] = a;
            }
            __syncthreads();
        }

        #pragma unroll
        for (int v = 0; v < VB; v++){
            int ob = s_out[v];
            if (ob < 0) continue;
            float val = acc[v];
            if (ident) val += ident[ob*COUT + tid];
            if (identx){
                int b = ob / Dout3, sp = ob - b*Dout3;
                const float* xp = identx + b*3*Dout3 + sp;
                val = fmaf(identw[tid],          xp[0],       val);
                val = fmaf(identw[COUT + tid],   xp[Dout3],   val);
                val = fmaf(identw[2*COUT + tid], xp[2*Dout3], val);
            }
            val = lrelu(val);
            if (out) out[ob*COUT + tid] = val;
            if (outh){
                __nv_bfloat16 h, l; split_bf16(val, h, l);
                outh[ob*COUT + tid] = h;
                outl[ob*COUT + tid] = l;
            }
        }
        __syncthreads();
    }
}

// ---------------- tensor conv via mma.sync (bf16 hi/lo split) ----------------
// 256 threads = 8 warps, 2D tiled: warp (wm,wn) owns 32 cout x 64 vox.
// Combo-major inner loop with all B frags preloaded per ks.
template<int CIN, int COUT>
__global__ void __launch_bounds__(256) convt_k(
    const __nv_bfloat16* __restrict__ inh, const __nv_bfloat16* __restrict__ inl,
    const __nv_bfloat16* __restrict__ wh,  const __nv_bfloat16* __restrict__ wl,
    const float* __restrict__ in_mask,
    const int* __restrict__ list, const int* __restrict__ cnt,
    int Din, int Dout, int stride,
    const float* __restrict__ ident,
    float* __restrict__ out,
    __nv_bfloat16* __restrict__ outh, __nv_bfloat16* __restrict__ outl)
{
    constexpr int CHUNKS = CIN/64;
    constexpr int NV = 128;
    constexpr int PITCH = 144;
    constexpr int MATB = 128*PITCH;

    extern __shared__ char dsm[];
    __shared__ int s_tap[27];
    __shared__ int s_ntap;
    __shared__ int s_base[27][NV];
    __shared__ int s_out[NV];

    const int tid  = threadIdx.x;
    const int w    = tid >> 5, lane = tid & 31;
    const int wm   = w & 3, wn = w >> 2;
    const int ybase = blockIdx.y * 128;
    const int Din3  = Din*Din*Din;
    const int Dout3 = Dout*Dout*Dout;
    const int n     = list ? *cnt : NB*Dout3;

    const int g  = lane >> 2;
    const int t4 = lane & 3;

    for (int vbase = blockIdx.x*NV; vbase < n; vbase += gridDim.x*NV){
        if (tid < NV){
            int vi = vbase + tid;
            int ob = -1;
            if (vi < n){
                int id = list ? list[vi] : vi;
                int vx = id % Dout; id /= Dout;
                int vy = id % Dout; id /= Dout;
                int vz = id % Dout; int vb = id / Dout;
                ob = vb*Dout3 + (vz*Dout + vy)*Dout + vx;
            }
            s_out[tid] = ob;
        }
        if (tid == 0) s_ntap = 0;
        __syncthreads();

        for (int t = 0; t < 27; t++){
            int base = -1;
            if (tid < NV && s_out[tid] >= 0){
                int id = list ? list[vbase + tid] : (vbase + tid);
                int vx = id % Dout; id /= Dout;
                int vy = id % Dout; id /= Dout;
                int vz = id % Dout; int vb = id / Dout;
                int kz = t/9, ky = (t/3)%3, kx = t%3;
                int iz = vz*stride - 1 + kz;
                int iy = vy*stride - 1 + ky;
                int ix = vx*stride - 1 + kx;
                if ((unsigned)iz < (unsigned)Din && (unsigned)iy < (unsigned)Din &&
                    (unsigned)ix < (unsigned)Din){
                    int sp = (iz*Din + iy)*Din + ix;
                    if (!in_mask || in_mask[vb*Din3 + sp] != 0.f)
                        base = (vb*Din3 + sp)*CIN;
                }
            }
            if (tid < NV) s_base[t][tid] = base;
            int any = __syncthreads_or(base >= 0);
            if (any && tid == 0) s_tap[s_ntap++] = t;
        }
        __syncthreads();
        const int ntap = s_ntap;
        const int nit  = ntap * CHUNKS;

        float acc[2][8][4];
        #pragma unroll
        for (int mi = 0; mi < 2; mi++)
            #pragma unroll
            for (int nt = 0; nt < 8; nt++)
                #pragma unroll
                for (int e = 0; e < 4; e++) acc[mi][nt][e] = 0.f;

        auto issue = [&](int it, int buf){
            int tap = s_tap[it/CHUNKS];
            int ch  = it%CHUNKS;
            char* Ah = dsm + buf*4*MATB;
            char* Al = Ah + MATB;
            char* Bh = Ah + 2*MATB;
            char* Bl = Ah + 3*MATB;
            const __nv_bfloat16* wsrcH = wh + (size_t)((tap*CHUNKS + ch)*COUT + ybase)*64;
            const __nv_bfloat16* wsrcL = wl + (size_t)((tap*CHUNKS + ch)*COUT + ybase)*64;
            #pragma unroll
            for (int j = 0; j < 4; j++){
                int idx = tid*4 + j;
                int row = idx >> 3, col = idx & 7;
                unsigned off = row*PITCH + col*16;
                asm volatile("cp.async.ca.shared.global [%0], [%1], 16;\n"
                    :: "r"(sm_addr(Ah) + off), "l"(wsrcH + row*64 + col*8));
                asm volatile("cp.async.ca.shared.global [%0], [%1], 16;\n"
                    :: "r"(sm_addr(Al) + off), "l"(wsrcL + row*64 + col*8));
                int base = s_base[tap][row];
                const __nv_bfloat16* bsrcH = (base >= 0) ? (inh + base + ch*64 + col*8) : inh;
                const __nv_bfloat16* bsrcL = (base >= 0) ? (inl + base + ch*64 + col*8) : inl;
                int sz = (base >= 0) ? 16 : 0;
                asm volatile("cp.async.ca.shared.global [%0], [%1], 16, %2;\n"
                    :: "r"(sm_addr(Bh) + off), "l"(bsrcH), "r"(sz));
                asm volatile("cp.async.ca.shared.global [%0], [%1], 16, %2;\n"
                    :: "r"(sm_addr(Bl) + off), "l"(bsrcL), "r"(sz));
            }
            asm volatile("cp.async.commit_group;\n");
        };

        if (nit > 0) issue(0, 0);
        for (int it = 0; it < nit; it++){
            int buf = it & 1;
            if (it + 1 < nit){
                issue(it + 1, buf ^ 1);
                asm volatile("cp.async.wait_group 1;\n");
            } else {
                asm volatile("cp.async.wait_group 0;\n");
            }
            __syncthreads();
            unsigned Ah = sm_addr(dsm) + buf*4*MATB;
            unsigned Al = Ah + MATB;
            unsigned Bh = Ah + 2*MATB;
            unsigned Bl = Ah + 3*MATB;
            unsigned arow0 = (unsigned)(wm*32 + (lane & 15))*PITCH + ((lane >> 4)*16);
            unsigned brow0 = (unsigned)(wn*64 + ((lane >> 4) & 1)*8 + (lane & 7))*PITCH
                           + (((lane >> 3) & 1)*16);
            #pragma unroll
            for (int ks = 0; ks < 4; ks++){
                uint32_t ah[2][4], al[2][4];
                #pragma unroll
                for (int mi = 0; mi < 2; mi++){
                    ldsm_x4(Ah + arow0 + mi*16*PITCH + ks*32,
                            ah[mi][0], ah[mi][1], ah[mi][2], ah[mi][3]);
                    ldsm_x4(Al + arow0 + mi*16*PITCH + ks*32,
                            al[mi][0], al[mi][1], al[mi][2], al[mi][3]);
                }
                uint32_t bh[16], bl[16];
                #pragma unroll
                for (int p = 0; p < 4; p++){
                    unsigned boff = brow0 + (unsigned)p*16*PITCH + ks*32;
                    ldsm_x4(Bh + boff, bh[4*p+0], bh[4*p+1], bh[4*p+2], bh[4*p+3]);
                    ldsm_x4(Bl + boff, bl[4*p+0], bl[4*p+1], bl[4*p+2], bl[4*p+3]);
                }
                #pragma unroll
                for (int nt = 0; nt < 8; nt++)
                    #pragma unroll
                    for (int mi = 0; mi < 2; mi++)
                        mma_bf16(acc[mi][nt], ah[mi], bh[2*nt], bh[2*nt+1]);
                #pragma unroll
                for (int nt = 0; nt < 8; nt++)
                    #pragma unroll
                    for (int mi = 0; mi < 2; mi++)
                        mma_bf16(acc[mi][nt], al[mi], bh[2*nt], bh[2*nt+1]);
                #pragma unroll
                for (int nt = 0; nt < 8; nt++)
                    #pragma unroll
                    for (int mi = 0; mi < 2; mi++)
                        mma_bf16(acc[mi][nt], ah[mi], bl[2*nt], bl[2*nt+1]);
            }
            __syncthreads();
        }

        // epilogue: lane holds D[cout=wm*32+mi*16+g(+8)][vox=wn*64+nt*8+t4*2(+1)]
        #pragma unroll
        for (int mi = 0; mi < 2; mi++){
            #pragma unroll
            for (int nt = 0; nt < 8; nt++){
                #pragma unroll
                for (int e = 0; e < 4; e++){
                    int v  = wn*64 + nt*8 + t4*2 + (e & 1);
                    int co = ybase + wm*32 + mi*16 + g + ((e >> 1)*8);
                    int ob = s_out[v];
                    if (ob < 0) continue;
                    float val = acc[mi][nt][e];
                    if (ident) val += ident[(size_t)ob*COUT + co];
                    val = lrelu(val);
                    size_t oi = (size_t)ob*COUT + co;
                    if (out) out[oi] = val;
                    if (outh){
                        __nv_bfloat16 h, l; split_bf16(val, h, l);
                        outh[oi] = h; outl[oi] = l;
                    }
                }
            }
        }
        __syncthreads();
    }
}

// ---------------- final pooled reduce ----------------
__global__ void reduce_k(const float* __restrict__ x4, float* __restrict__ out){
    int b  = blockIdx.x;
    int oc = threadIdx.x;
    const float* p = x4 + b*512*128 + oc;
    float s = 0.f, mx = -3.402823466e38f;
    #pragma unroll 8
    for (int sp = 0; sp < 512; sp++){
        float v = p[sp*128];
        s += v; mx = fmaxf(mx, v);
    }
    out[b*256 + oc]       = s * (1.f/512.f);
    out[b*256 + 128 + oc] = mx;
}

// ---------------- launch ----------------
extern "C" void kernel_launch(void* const* d_in, const int* in_sizes, int n_in,
                              void* d_out, int out_size){
    const float* x    = (const float*)d_in[0];
    const float* mask = (const float*)d_in[1];
    float* out = (float*)d_out;

    float *t1,*xd1,*xd2,*x4,*m2,*m3;
    int *l1,*l2,*l3,*cnt;
    cudaGetSymbolAddress((void**)&t1 , g_t1 );
    cudaGetSymbolAddress((void**)&xd1, g_xd1);
    cudaGetSymbolAddress((void**)&xd2, g_xd2);
    cudaGetSymbolAddress((void**)&x4 , g_x4 );
    cudaGetSymbolAddress((void**)&m2 , g_m2 );
    cudaGetSymbolAddress((void**)&m3 , g_m3 );
    cudaGetSymbolAddress((void**)&l1 , g_list1);
    cudaGetSymbolAddress((void**)&l2 , g_list2);
    cudaGetSymbolAddress((void**)&l3 , g_list3);
    cudaGetSymbolAddress((void**)&cnt, g_cnt);

    float *w1ar,*w1br,*w1dr;
    cudaGetSymbolAddress((void**)&w1ar, g_w1a);
    cudaGetSymbolAddress((void**)&w1br, g_w1b);
    cudaGetSymbolAddress((void**)&w1dr, g_w1d);

    __nv_bfloat16 *wd1h,*wd1l,*w2ah,*w2al,*w2bh,*w2bl,*wd2h,*wd2l,
                  *w3ah,*w3al,*w3bh,*w3bl,*wd3h,*wd3l;
    cudaGetSymbolAddress((void**)&wd1h, g_wd1_h); cudaGetSymbolAddress((void**)&wd1l, g_wd1_l);
    cudaGetSymbolAddress((void**)&w2ah, g_w2a_h); cudaGetSymbolAddress((void**)&w2al, g_w2a_l);
    cudaGetSymbolAddress((void**)&w2bh, g_w2b_h); cudaGetSymbolAddress((void**)&w2bl, g_w2b_l);
    cudaGetSymbolAddress((void**)&wd2h, g_wd2_h); cudaGetSymbolAddress((void**)&wd2l, g_wd2_l);
    cudaGetSymbolAddress((void**)&w3ah, g_w3a_h); cudaGetSymbolAddress((void**)&w3al, g_w3a_l);
    cudaGetSymbolAddress((void**)&w3bh, g_w3b_h); cudaGetSymbolAddress((void**)&w3bl, g_w3b_l);
    cudaGetSymbolAddress((void**)&wd3h, g_wd3_h); cudaGetSymbolAddress((void**)&wd3l, g_wd3_l);

    __nv_bfloat16 *x1h,*x1l,*xd1h,*xd1l,*t2h,*t2l,*x2h,*x2l,*xd2h,*xd2l,*t3h,*t3l,*x3h,*x3l;
    cudaGetSymbolAddress((void**)&x1h,  g_x1h ); cudaGetSymbolAddress((void**)&x1l,  g_x1l );
    cudaGetSymbolAddress((void**)&xd1h, g_xd1h); cudaGetSymbolAddress((void**)&xd1l, g_xd1l);
    cudaGetSymbolAddress((void**)&t2h,  g_t2h ); cudaGetSymbolAddress((void**)&t2l,  g_t2l );
    cudaGetSymbolAddress((void**)&x2h,  g_x2h ); cudaGetSymbolAddress((void**)&x2l,  g_x2l );
    cudaGetSymbolAddress((void**)&xd2h, g_xd2h); cudaGetSymbolAddress((void**)&xd2l, g_xd2l);
    cudaGetSymbolAddress((void**)&t3h,  g_t3h ); cudaGetSymbolAddress((void**)&t3l,  g_t3l );
    cudaGetSymbolAddress((void**)&x3h,  g_x3h ); cudaGetSymbolAddress((void**)&x3l,  g_x3l );

    RepackArgs ra;
    {
        const float* src[3] = {(const float*)d_in[2], (const float*)d_in[4],
                               (const float*)d_in[3]};
        float* dst[3] = {w1ar, w1dr, w1br};
        const int cins[3]  = {3, 3, 64};
        const int couts[3] = {64,64, 64};
        const int k3s[3]   = {27, 1, 27};
        int off = 0;
        for (int i = 0; i < 3; i++){
            ra.src[i]=src[i]; ra.dst[i]=dst[i];
            ra.cin[i]=cins[i]; ra.cout[i]=couts[i]; ra.k3[i]=k3s[i];
            ra.start[i]=off; off += cins[i]*couts[i]*k3s[i];
        }
        ra.ntot = off;
    }
    RepackMMA rm;
    {
        const float* src[7] = {(const float*)d_in[5], (const float*)d_in[6],
                               (const float*)d_in[7], (const float*)d_in[8],
                               (const float*)d_in[9], (const float*)d_in[10],
                               (const float*)d_in[11]};
        __nv_bfloat16* dh[7] = {wd1h, w2ah, w2bh, wd2h, w3ah, w3bh, wd3h};
        __nv_bfloat16* dl[7] = {wd1l, w2al, w2bl, wd2l, w3al, w3bl, wd3l};
        const int cins[7]  = {64, 128, 128, 128, 256, 256, 256};
        const int couts[7] = {128,128, 128, 256, 256, 256, 128};
        int off = 0;
        for (int i = 0; i < 7; i++){
            rm.src[i]=src[i]; rm.dh[i]=dh[i]; rm.dl[i]=dl[i];
            rm.cin[i]=cins[i]; rm.cout[i]=couts[i];
            rm.start[i]=off; off += cins[i]*couts[i]*27;
        }
        rm.ntot = off;
    }

    const int DSM = 2*4*128*144;   // 147456 B
    cudaFuncSetAttribute(convt_k<64,128>,  cudaFuncAttributeMaxDynamicSharedMemorySize, DSM);
    cudaFuncSetAttribute(convt_k<128,128>, cudaFuncAttributeMaxDynamicSharedMemorySize, DSM);
    cudaFuncSetAttribute(convt_k<128,256>, cudaFuncAttributeMaxDynamicSharedMemorySize, DSM);
    cudaFuncSetAttribute(convt_k<256,256>, cudaFuncAttributeMaxDynamicSharedMemorySize, DSM);
    cudaFuncSetAttribute(convt_k<256,128>, cudaFuncAttributeMaxDynamicSharedMemorySize, DSM);

    repack_all_k<<<(ra.ntot + 255)/256, 256>>>(ra);
    repack_mma_k<<<(rm.ntot + 255)/256, 256>>>(rm);
    down_mask_k<<<(NB*32768 + 255)/256, 256>>>(mask, m2, 64, 32);
    fuse_k<<<(NB*262144 + NB*32768 + NB*4096 + 255)/256, 256>>>(mask, m2, m3, l1, l2, cnt);
    build_list_k<<<(NB*4096 + 255)/256, 256>>>(m3, NB*4096, l3, cnt+2);

    // ---- stage 1 (scalar, sparse); stage-1b emits x1 as bf16 hi/lo only ----
    conv_s_k<3,64,3,8><<<2048,64>>>(x, w1ar, mask, l1, cnt+0, 64, 64, t1);
    convp_k<64,64,16,8><<<4096,64>>>(t1, w1br, mask, l1, cnt+0, 64,64,1,
                                     nullptr, x, w1dr, nullptr, x1h, x1l);
    // ---- down1 (tensor; mask-gated gather from 64^3, l2 outputs) ----
    convt_k<64,128><<<dim3(512,1),256,DSM>>>(x1h, x1l, wd1h, wd1l, mask,
                                             l2, cnt+1, 64,32,2, nullptr,
                                             xd1, xd1h, xd1l);
    // ---- stage 2 (tensor) ----
    convt_k<128,128><<<dim3(512,1),256,DSM>>>(xd1h, xd1l, w2ah, w2al, m2,
                                              l2, cnt+1, 32,32,1, nullptr,
                                              nullptr, t2h, t2l);
    fill_k<<<2048,256>>>(xd1, m2, nullptr, x2h, x2l, 128, NB*32768*128);
    convt_k<128,128><<<dim3(512,1),256,DSM>>>(t2h, t2l, w2bh, w2bl, m2,
                                              l2, cnt+1, 32,32,1, xd1,
                                              nullptr, x2h, x2l);
    // ---- down2 (tensor, dense, stride 2; fp32 needed as stage-3b ident) ----
    convt_k<128,256><<<dim3(64,2),256,DSM>>>(x2h, x2l, wd2h, wd2l, nullptr,
                                             nullptr, nullptr, 32,16,2, nullptr,
                                             xd2, xd2h, xd2l);
    // ---- stage 3 (tensor) ----
    convt_k<256,256><<<dim3(64,2),256,DSM>>>(xd2h, xd2l, w3ah, w3al, nullptr,
                                             l3, cnt+2, 16,16,1, nullptr,
                                             nullptr, t3h, t3l);
    fill_k<<<1024,256>>>(xd2, nullptr, nullptr, x3h, x3l, 256, NB*4096*256);
    convt_k<256,256><<<dim3(64,2),256,DSM>>>(t3h, t3l, w3bh, w3bl, m3,
                                             l3, cnt+2, 16,16,1, xd2,
                                             nullptr, x3h, x3l);
    // ---- down3 (tensor, dense, stride 2) ----
    convt_k<256,128><<<dim3(8,1),256,DSM>>>(x3h, x3l, wd3h, wd3l, nullptr,
                                            nullptr, nullptr, 16,8,2, nullptr,
                                            x4, nullptr, nullptr);
    reduce_k<<<2,128>>>(x4, out);
}